// round 6
// baseline (speedup 1.0000x reference)
#include <cuda_runtime.h>
#include <cuda_fp16.h>
#include <cstdint>

// Problem constants
#define BATCH  2048
#define NITEMS 20000
#define KPAD   20032   // NITEMS padded to multiple of 64
#define EMB    512
#define HID    1024    // 2*D

// ---------------------------------------------------------------------------
// Scratch (no allocations -> __device__ globals), all fp16 GEMM operands
// ---------------------------------------------------------------------------
__device__ __half g_noisyh[(size_t)BATCH * KPAD];    // masked likes fp16, padded
__device__ __half g_W1h[(size_t)HID * KPAD];         // enc_w1^T [1024][20032]
__device__ __half g_W2h[(size_t)EMB * HID];          // enc_w2^T [512][1024]
__device__ __half g_W3h[(size_t)HID * EMB];          // lk_w1^T  [1024][512]
__device__ __half g_W4h[(size_t)NITEMS * HID];       // lk_w2^T  [20000][1024]
__device__ __half g_W5h[(size_t)HID * EMB];          // rc_w1^T
__device__ __half g_W6h[(size_t)NITEMS * HID];       // rc_w2^T
__device__ __half g_Hh[(size_t)BATCH * HID];         // hidden fp16
__device__ float  g_E[(size_t)BATCH * EMB];          // embed f32
__device__ __half g_Eh[(size_t)BATCH * EMB];         // embed fp16
__device__ __half g_Nrmh[(size_t)BATCH * EMB];       // normalized fp16
__device__ float  g_part[16 * NITEMS];
__device__ int    g_mask_mode;  // 0=u8, 1=i32, 2=f32

// ---------------------------------------------------------------------------
// PTX helpers (arch-generic sm_80-era instructions; no sm_103a-only ops)
// ---------------------------------------------------------------------------
__device__ __forceinline__ uint32_t smem_u32(const void* p) {
    uint32_t a;
    asm("{ .reg .u64 t; cvta.to.shared.u64 t, %1; cvt.u32.u64 %0, t; }"
        : "=r"(a) : "l"(p));
    return a;
}
__device__ __forceinline__ void cp16(uint32_t dst, const void* src, int sz) {
    asm volatile("cp.async.cg.shared.global [%0], [%1], 16, %2;"
        :: "r"(dst), "l"(src), "r"(sz));
}
#define CP_COMMIT() asm volatile("cp.async.commit_group;" ::: "memory")
#define CP_WAIT(n)  asm volatile("cp.async.wait_group %0;" :: "n"(n) : "memory")

#define LDSM_X4(r, addr) \
    asm volatile("ldmatrix.sync.aligned.m8n8.x4.shared.b16 {%0,%1,%2,%3}, [%4];" \
        : "=r"((r)[0]), "=r"((r)[1]), "=r"((r)[2]), "=r"((r)[3]) : "r"(addr))

__device__ __forceinline__ void mma16816(float* d, const uint32_t* a,
                                         uint32_t b0, uint32_t b1) {
    asm volatile(
        "mma.sync.aligned.m16n8k16.row.col.f32.f16.f16.f32 "
        "{%0,%1,%2,%3}, {%4,%5,%6,%7}, {%8,%9}, {%0,%1,%2,%3};"
        : "+f"(d[0]), "+f"(d[1]), "+f"(d[2]), "+f"(d[3])
        : "r"(a[0]), "r"(a[1]), "r"(a[2]), "r"(a[3]), "r"(b0), "r"(b1));
}

// ---------------------------------------------------------------------------
// Small kernels
// ---------------------------------------------------------------------------
__global__ void probe_mask_kernel(const unsigned int* __restrict__ w) {
    __shared__ int s_other, s_f1, s_i1;
    if (threadIdx.x == 0) { s_other = 0; s_f1 = 0; s_i1 = 0; }
    __syncthreads();
    int lo = 0, lf = 0, li = 0;
    for (int i = threadIdx.x; i < 65536; i += blockDim.x) {
        unsigned v = w[i];
        if (v == 0u) continue;
        else if (v == 1u) li++;
        else if (v == 0x3F800000u) lf++;
        else lo++;
    }
    atomicAdd(&s_other, lo); atomicAdd(&s_f1, lf); atomicAdd(&s_i1, li);
    __syncthreads();
    if (threadIdx.x == 0) {
        int mode;
        if (s_other > 1024) mode = 0;
        else if (s_f1 >= s_i1) mode = 2;
        else mode = 1;
        g_mask_mode = mode;
    }
}

// Fused: noisy = where(mask,0,likes) -> fp16 padded  AND  column partial sums
// of likes (for popular). One pass over likes. grid (ceil(KPAD/256), 16).
__global__ void premask_popular_kernel(const float* __restrict__ likes,
                                       const void* __restrict__ mask,
                                       __half* __restrict__ noisy,
                                       float* __restrict__ part) {
    const int mode = g_mask_mode;
    const int col = blockIdx.x * 256 + threadIdx.x;
    if (col >= KPAD) return;
    const int r0 = blockIdx.y * 128;

    if (col >= NITEMS) {  // padding region: zero noisy, no popular
        const __half hz = __float2half_rn(0.f);
        for (int r = 0; r < 128; r++)
            noisy[(size_t)(r0 + r) * KPAD + col] = hz;
        return;
    }

    const unsigned char* m8 = (const unsigned char*)mask;
    const int*           mi = (const int*)mask;
    const float*         mf = (const float*)mask;

    float sum = 0.f;
    #pragma unroll 4
    for (int r = 0; r < 128; r++) {
        size_t e = (size_t)(r0 + r) * NITEMS + col;
        float v = likes[e];
        sum += v;
        bool drop;
        if (mode == 0)      drop = (m8[e] != 0);
        else if (mode == 1) drop = (mi[e] != 0);
        else                drop = (mf[e] != 0.f);
        noisy[(size_t)(r0 + r) * KPAD + col] = __float2half_rn(drop ? 0.f : v);
    }
    part[blockIdx.y * NITEMS + col] = sum;
}

__global__ void popular_reduce_kernel(const float* __restrict__ part,
                                      float* __restrict__ out_pop) {
    int i = blockIdx.x * 256 + threadIdx.x;
    if (i >= NITEMS) return;
    float s = 0.f;
    #pragma unroll
    for (int c = 0; c < 16; c++) s += part[c * NITEMS + i];
    out_pop[i] = s * (1.0f / (float)BATCH);
}

// per-row l2 normalize; emit fp16 normalized AND fp16 copy of E
__global__ void norm_half_kernel(const float* __restrict__ E,
                                 __half* __restrict__ Nrmh,
                                 __half* __restrict__ Eh) {
    int row = blockIdx.x;
    int t = threadIdx.x;   // 128 threads, EMB=512 -> one float4 each
    float4 v = reinterpret_cast<const float4*>(E + (size_t)row * EMB)[t];
    float ss = v.x * v.x + v.y * v.y + v.z * v.z + v.w * v.w;
    #pragma unroll
    for (int o = 16; o > 0; o >>= 1)
        ss += __shfl_xor_sync(0xFFFFFFFFu, ss, o);
    __shared__ float ws[4];
    if ((t & 31) == 0) ws[t >> 5] = ss;
    __syncthreads();
    float tot = ws[0] + ws[1] + ws[2] + ws[3];
    float inv = rsqrtf(fmaxf(tot, 1e-12f));
    __half2* eh = reinterpret_cast<__half2*>(Eh + (size_t)row * EMB + t * 4);
    eh[0] = __floats2half2_rn(v.x, v.y);
    eh[1] = __floats2half2_rn(v.z, v.w);
    __half2* nh = reinterpret_cast<__half2*>(Nrmh + (size_t)row * EMB + t * 4);
    nh[0] = __floats2half2_rn(v.x * inv, v.y * inv);
    nh[1] = __floats2half2_rn(v.z * inv, v.w * inv);
}

// transpose + convert: in f32 [R][C] -> out fp16 [C][Rp], zero for r >= R
__global__ void transpose_half_kernel(const float* __restrict__ in,
                                      __half* __restrict__ out,
                                      int R, int C, int Rp) {
    __shared__ float t[32][33];
    int c0 = blockIdx.x * 32, r0 = blockIdx.y * 32;
    int x = threadIdx.x, y = threadIdx.y;
    #pragma unroll
    for (int i = 0; i < 32; i += 8) {
        int r = r0 + y + i, c = c0 + x;
        t[y + i][x] = (r < R && c < C) ? in[(size_t)r * C + c] : 0.f;
    }
    __syncthreads();
    #pragma unroll
    for (int i = 0; i < 32; i += 8) {
        int cc = c0 + y + i, rr = r0 + x;
        if (cc < C && rr < Rp)
            out[(size_t)cc * Rp + rr] = __float2half_rn(t[x][y + i]);
    }
}

// ---------------------------------------------------------------------------
// fp16 tensor-core GEMM: C[M,N] = act(A[M,K] @ Bt[N,K]^T + bias)
//   A: fp16 [M][lda] K-major;  Bt: fp16 [N][ldb] K-major.
//   CTA tile 128x128, BK=64, 3-stage cp.async (96KB smem), 2 CTAs/SM,
//   8 warps (2m x 4n, 64x32 each) — proven fastest config (R4).
// ---------------------------------------------------------------------------
enum { ACT_RELU = 0, ACT_SIG = 1, ACT_NEG = 2 };
#define BK 64
#define NSTAGE 3
#define ASZ 16384                 // 128 rows * 128B
#define SSZ 32768                 // A + B per stage

template<int ACT, bool HAS_BIAS, bool OUT_HALF>
__global__ __launch_bounds__(256, 2)
void hmma_gemm(const __half* __restrict__ A, const __half* __restrict__ Bt,
               const float* __restrict__ bias, void* __restrict__ Cout,
               int M, int N, int K, int lda, int ldb) {
    extern __shared__ __align__(128) char smem[];
    const uint32_t sbase = smem_u32(smem);

    const int tid = threadIdx.x;
    const int lane = tid & 31, wid = tid >> 5;
    const int wm = (wid & 1) * 64;        // warp m offset in tile
    const int wn = (wid >> 1) * 32;       // warp n offset in tile
    const int m0 = blockIdx.x * 128;
    const int n0 = blockIdx.y * 128;
    const int nch = K / BK;

    float acc[4][4][4];
    #pragma unroll
    for (int i = 0; i < 4; i++)
        #pragma unroll
        for (int j = 0; j < 4; j++)
            #pragma unroll
            for (int q = 0; q < 4; q++) acc[i][j][q] = 0.f;

    // ---- stage loader ----
    auto load_stage = [&](int ch, int st) {
        const int k0 = ch * BK;
        const uint32_t sA = sbase + st * SSZ;
        const uint32_t sB = sA + ASZ;
        #pragma unroll
        for (int u = 0; u < 4; u++) {
            int idx = tid + u * 256;
            int r = idx >> 3, c = idx & 7;
            const __half* src = A + (size_t)(m0 + r) * lda + k0 + c * 8;
            cp16(sA + r * 128 + ((c ^ (r & 7)) << 4), src, 16);
        }
        #pragma unroll
        for (int u = 0; u < 4; u++) {
            int idx = tid + u * 256;
            int r = idx >> 3, c = idx & 7;
            int n = n0 + r;
            const __half* src = Bt + (size_t)n * ldb + k0 + c * 8;
            cp16(sB + r * 128 + ((c ^ (r & 7)) << 4), src, (n < N) ? 16 : 0);
        }
        CP_COMMIT();
    };

    // ldmatrix lane addressing (swizzle bits constant per lane)
    const int aRow = wm + (lane & 15);
    const int aKsel = lane >> 4;            // 0/1 -> +16B within 32B k16
    const int bRow = wn + ((lane >> 4) << 3) + (lane & 7);
    const int bKsel = (lane >> 3) & 1;
    const int swz = lane & 7;

    load_stage(0, 0);
    load_stage(1, 1);

    for (int i = 0; i < nch; i++) {
        const int j = i + NSTAGE - 1;
        if (j < nch) load_stage(j, j % NSTAGE);
        else         CP_COMMIT();           // empty group keeps wait count aligned
        CP_WAIT(NSTAGE - 1);
        __syncthreads();

        const uint32_t sA = sbase + (i % NSTAGE) * SSZ;
        const uint32_t sB = sA + ASZ;
        #pragma unroll
        for (int kk = 0; kk < 4; kk++) {
            uint32_t a[4][4], b[2][4];
            const uint32_t aByte = ((2 * kk + aKsel) ^ swz) << 4;
            const uint32_t bByte = ((2 * kk + bKsel) ^ swz) << 4;
            #pragma unroll
            for (int mf = 0; mf < 4; mf++)
                LDSM_X4(a[mf], sA + (aRow + 16 * mf) * 128 + aByte);
            #pragma unroll
            for (int nf2 = 0; nf2 < 2; nf2++)
                LDSM_X4(b[nf2], sB + (bRow + 16 * nf2) * 128 + bByte);
            #pragma unroll
            for (int mf = 0; mf < 4; mf++)
                #pragma unroll
                for (int nf = 0; nf < 4; nf++)
                    mma16816(acc[mf][nf], a[mf],
                             b[nf >> 1][(nf & 1) * 2],
                             b[nf >> 1][(nf & 1) * 2 + 1]);
        }
        __syncthreads();
    }

    // ---- epilogue ----
    #pragma unroll
    for (int mf = 0; mf < 4; mf++) {
        const int row = m0 + wm + mf * 16 + (lane >> 2);
        #pragma unroll
        for (int nf = 0; nf < 4; nf++) {
            const int col = n0 + wn + nf * 8 + 2 * (lane & 3);
            if (col >= N) continue;
            float2 lo = make_float2(acc[mf][nf][0], acc[mf][nf][1]);
            float2 hi = make_float2(acc[mf][nf][2], acc[mf][nf][3]);
            if (HAS_BIAS) {
                float2 bb = *reinterpret_cast<const float2*>(bias + col);
                lo.x += bb.x; lo.y += bb.y;
                hi.x += bb.x; hi.y += bb.y;
            }
            if (ACT == ACT_RELU) {
                lo.x = fmaxf(lo.x, 0.f); lo.y = fmaxf(lo.y, 0.f);
                hi.x = fmaxf(hi.x, 0.f); hi.y = fmaxf(hi.y, 0.f);
            } else if (ACT == ACT_SIG) {
                lo.x = 1.f / (1.f + __expf(-lo.x));
                lo.y = 1.f / (1.f + __expf(-lo.y));
                hi.x = 1.f / (1.f + __expf(-hi.x));
                hi.y = 1.f / (1.f + __expf(-hi.y));
            } else {
                lo.x = -lo.x; lo.y = -lo.y;
                hi.x = -hi.x; hi.y = -hi.y;
            }
            if (OUT_HALF) {
                __half* C = (__half*)Cout;
                *reinterpret_cast<__half2*>(C + (size_t)row * N + col) =
                    __floats2half2_rn(lo.x, lo.y);
                *reinterpret_cast<__half2*>(C + (size_t)(row + 8) * N + col) =
                    __floats2half2_rn(hi.x, hi.y);
            } else {
                float* C = (float*)Cout;
                *reinterpret_cast<float2*>(C + (size_t)row * N + col) = lo;
                *reinterpret_cast<float2*>(C + (size_t)(row + 8) * N + col) = hi;
            }
        }
    }
}

// ---------------------------------------------------------------------------
// Launch: dual-stream graph. Side stream s1 does all weight transposes +
// popular_reduce, hidden behind premask + gemm1 (tensor-bound).
// Host-side overhead only occurs at capture time, not during graph replay.
// ---------------------------------------------------------------------------
extern "C" void kernel_launch(void* const* d_in, const int* in_sizes, int n_in,
                              void* d_out, int out_size) {
    const float* likes  = (const float*)d_in[1];
    const void*  nmask  = d_in[2];
    const float* enc_w1 = (const float*)d_in[3];
    const float* enc_b1 = (const float*)d_in[4];
    const float* enc_w2 = (const float*)d_in[5];
    const float* enc_b2 = (const float*)d_in[6];
    const float* lk_w1  = (const float*)d_in[7];
    const float* lk_b1  = (const float*)d_in[8];
    const float* lk_w2  = (const float*)d_in[9];
    const float* lk_b2  = (const float*)d_in[10];
    const float* rc_w1  = (const float*)d_in[11];
    const float* rc_b1  = (const float*)d_in[12];
    const float* rc_w2  = (const float*)d_in[13];
    const float* rc_b2  = (const float*)d_in[14];

    float* out       = (float*)d_out;
    float* out_likes = out;
    float* out_sim   = out_likes + (size_t)BATCH * NITEMS;
    float* out_rec   = out_sim + (size_t)BATCH * BATCH;
    float* out_pop   = out_rec + (size_t)BATCH * NITEMS;

    __half *noisyh, *W1h, *W2h, *W3h, *W4h, *W5h, *W6h, *Hh, *Eh, *Nrmh;
    float *E, *part;
    cudaGetSymbolAddress((void**)&noisyh, g_noisyh);
    cudaGetSymbolAddress((void**)&W1h, g_W1h);
    cudaGetSymbolAddress((void**)&W2h, g_W2h);
    cudaGetSymbolAddress((void**)&W3h, g_W3h);
    cudaGetSymbolAddress((void**)&W4h, g_W4h);
    cudaGetSymbolAddress((void**)&W5h, g_W5h);
    cudaGetSymbolAddress((void**)&W6h, g_W6h);
    cudaGetSymbolAddress((void**)&Hh, g_Hh);
    cudaGetSymbolAddress((void**)&E, g_E);
    cudaGetSymbolAddress((void**)&Eh, g_Eh);
    cudaGetSymbolAddress((void**)&Nrmh, g_Nrmh);
    cudaGetSymbolAddress((void**)&part, g_part);

    const int smem = NSTAGE * SSZ;  // 96KB
    cudaFuncSetAttribute(hmma_gemm<ACT_RELU, true, true>,
                         cudaFuncAttributeMaxDynamicSharedMemorySize, smem);
    cudaFuncSetAttribute(hmma_gemm<ACT_RELU, true, false>,
                         cudaFuncAttributeMaxDynamicSharedMemorySize, smem);
    cudaFuncSetAttribute(hmma_gemm<ACT_SIG, true, false>,
                         cudaFuncAttributeMaxDynamicSharedMemorySize, smem);
    cudaFuncSetAttribute(hmma_gemm<ACT_NEG, false, false>,
                         cudaFuncAttributeMaxDynamicSharedMemorySize, smem);

    // side stream + fork/join events (created once; graph replay has no host cost)
    static cudaStream_t s1 = nullptr;
    static cudaEvent_t eFork = nullptr, eW1 = nullptr, ePM = nullptr, eRest = nullptr;
    if (s1 == nullptr) {
        cudaStreamCreateWithFlags(&s1, cudaStreamNonBlocking);
        cudaEventCreateWithFlags(&eFork, cudaEventDisableTiming);
        cudaEventCreateWithFlags(&eW1,   cudaEventDisableTiming);
        cudaEventCreateWithFlags(&ePM,   cudaEventDisableTiming);
        cudaEventCreateWithFlags(&eRest, cudaEventDisableTiming);
    }

    dim3 tb(32, 8);

    // ---- main stream: probe -> premask ----
    probe_mask_kernel<<<1, 256>>>((const unsigned int*)nmask);
    cudaEventRecord(eFork, 0);
    cudaStreamWaitEvent(s1, eFork, 0);           // fork s1 into the capture

    premask_popular_kernel<<<dim3((KPAD + 255) / 256, 16), 256>>>(
        likes, nmask, noisyh, part);
    cudaEventRecord(ePM, 0);

    // ---- s1: all weight transposes + popular reduce (hidden under gemm1) ----
    transpose_half_kernel<<<dim3(HID / 32, KPAD / 32), tb, 0, s1>>>(
        enc_w1, W1h, NITEMS, HID, KPAD);
    cudaEventRecord(eW1, s1);
    transpose_half_kernel<<<dim3(EMB / 32, HID / 32), tb, 0, s1>>>(
        enc_w2, W2h, HID, EMB, HID);
    transpose_half_kernel<<<dim3(HID / 32, EMB / 32), tb, 0, s1>>>(
        lk_w1, W3h, EMB, HID, EMB);
    transpose_half_kernel<<<dim3(HID / 32, EMB / 32), tb, 0, s1>>>(
        rc_w1, W5h, EMB, HID, EMB);
    transpose_half_kernel<<<dim3((NITEMS + 31) / 32, HID / 32), tb, 0, s1>>>(
        lk_w2, W4h, HID, NITEMS, HID);
    transpose_half_kernel<<<dim3((NITEMS + 31) / 32, HID / 32), tb, 0, s1>>>(
        rc_w2, W6h, HID, NITEMS, HID);
    cudaStreamWaitEvent(s1, ePM, 0);
    popular_reduce_kernel<<<(NITEMS + 255) / 256, 256, 0, s1>>>(part, out_pop);
    cudaEventRecord(eRest, s1);

    // ---- main: gemm1 needs only W1h + noisyh ----
    cudaStreamWaitEvent(0, eW1, 0);
    hmma_gemm<ACT_RELU, true, true><<<dim3(BATCH / 128, HID / 128), 256, smem>>>(
        noisyh, W1h, enc_b1, Hh, BATCH, HID, KPAD, KPAD, KPAD);

    // join: everything else needs the remaining transposes
    cudaStreamWaitEvent(0, eRest, 0);

    // encoder layer 2 + norm
    hmma_gemm<ACT_RELU, true, false><<<dim3(BATCH / 128, EMB / 128), 256, smem>>>(
        Hh, W2h, enc_b2, E, BATCH, EMB, HID, HID, HID);
    norm_half_kernel<<<BATCH, 128>>>(E, Nrmh, Eh);

    // user_sim = -(Nrm @ Nrm^T)
    hmma_gemm<ACT_NEG, false, false><<<dim3(BATCH / 128, BATCH / 128), 256, smem>>>(
        Nrmh, Nrmh, nullptr, out_sim, BATCH, BATCH, EMB, EMB, EMB);

    // likes head
    hmma_gemm<ACT_RELU, true, true><<<dim3(BATCH / 128, HID / 128), 256, smem>>>(
        Eh, W3h, lk_b1, Hh, BATCH, HID, EMB, EMB, EMB);
    hmma_gemm<ACT_SIG, true, false>
        <<<dim3(BATCH / 128, (NITEMS + 127) / 128), 256, smem>>>(
        Hh, W4h, lk_b2, out_likes, BATCH, NITEMS, HID, HID, HID);

    // rec head
    hmma_gemm<ACT_RELU, true, true><<<dim3(BATCH / 128, HID / 128), 256, smem>>>(
        Eh, W5h, rc_b1, Hh, BATCH, HID, EMB, EMB, EMB);
    hmma_gemm<ACT_SIG, true, false>
        <<<dim3(BATCH / 128, (NITEMS + 127) / 128), 256, smem>>>(
        Hh, W6h, rc_b2, out_rec, BATCH, NITEMS, HID, HID, HID);
}

// round 7
// speedup vs baseline: 1.1402x; 1.1402x over previous
#include <cuda_runtime.h>
#include <cuda_fp16.h>
#include <cstdint>

// Problem constants
#define BATCH  2048
#define NITEMS 20000
#define KPAD   20032   // NITEMS padded to multiple of 64
#define EMB    512
#define HID    1024    // 2*D

// ---------------------------------------------------------------------------
// Scratch (no allocations -> __device__ globals)
// Weights are CONVERTED (f32->fp16) in-place layout [K][N] row-major and
// consumed by the trans-B GEMM path -- no transposes needed.
// ---------------------------------------------------------------------------
__device__ __half g_noisyh[(size_t)BATCH * KPAD];    // masked likes fp16, padded
__device__ __half g_W1c[(size_t)KPAD * HID];         // enc_w1 fp16 [20032][1024] (zero-pad rows)
__device__ __half g_W2c[(size_t)HID * EMB];          // enc_w2 fp16 [1024][512]
__device__ __half g_Wlr[(size_t)EMB * (2 * HID)];    // [512][2048] = lk_w1 ++ rc_w1 (cols)
__device__ __half g_W4c[(size_t)HID * NITEMS];       // lk_w2 fp16 [1024][20000]
__device__ __half g_W6c[(size_t)HID * NITEMS];       // rc_w2 fp16 [1024][20000]
__device__ float  g_blr[2 * HID];                    // lk_b1 ++ rc_b1
__device__ __half g_Hh[(size_t)BATCH * HID];         // encoder hidden fp16
__device__ __half g_Hh2[(size_t)BATCH * 2 * HID];    // fused head hiddens fp16
__device__ float  g_E[(size_t)BATCH * EMB];          // embed f32
__device__ __half g_Eh[(size_t)BATCH * EMB];         // embed fp16
__device__ __half g_Nrmh[(size_t)BATCH * EMB];       // normalized fp16
__device__ float  g_part[16 * NITEMS];
__device__ int    g_mask_mode;  // 0=u8, 1=i32, 2=f32

// ---------------------------------------------------------------------------
// PTX helpers (arch-generic sm_80-era instructions)
// ---------------------------------------------------------------------------
__device__ __forceinline__ uint32_t smem_u32(const void* p) {
    uint32_t a;
    asm("{ .reg .u64 t; cvta.to.shared.u64 t, %1; cvt.u32.u64 %0, t; }"
        : "=r"(a) : "l"(p));
    return a;
}
__device__ __forceinline__ void cp16(uint32_t dst, const void* src, int sz) {
    asm volatile("cp.async.cg.shared.global [%0], [%1], 16, %2;"
        :: "r"(dst), "l"(src), "r"(sz));
}
#define CP_COMMIT() asm volatile("cp.async.commit_group;" ::: "memory")
#define CP_WAIT(n)  asm volatile("cp.async.wait_group %0;" :: "n"(n) : "memory")

#define LDSM_X4(r, addr) \
    asm volatile("ldmatrix.sync.aligned.m8n8.x4.shared.b16 {%0,%1,%2,%3}, [%4];" \
        : "=r"((r)[0]), "=r"((r)[1]), "=r"((r)[2]), "=r"((r)[3]) : "r"(addr))

#define LDSM_X4_T(r, addr) \
    asm volatile("ldmatrix.sync.aligned.m8n8.x4.trans.shared.b16 {%0,%1,%2,%3}, [%4];" \
        : "=r"((r)[0]), "=r"((r)[1]), "=r"((r)[2]), "=r"((r)[3]) : "r"(addr))

__device__ __forceinline__ void mma16816(float* d, const uint32_t* a,
                                         uint32_t b0, uint32_t b1) {
    asm volatile(
        "mma.sync.aligned.m16n8k16.row.col.f32.f16.f16.f32 "
        "{%0,%1,%2,%3}, {%4,%5,%6,%7}, {%8,%9}, {%0,%1,%2,%3};"
        : "+f"(d[0]), "+f"(d[1]), "+f"(d[2]), "+f"(d[3])
        : "r"(a[0]), "r"(a[1]), "r"(a[2]), "r"(a[3]), "r"(b0), "r"(b1));
}

// ---------------------------------------------------------------------------
// Small kernels
// ---------------------------------------------------------------------------
__global__ void probe_mask_kernel(const unsigned int* __restrict__ w) {
    __shared__ int s_other, s_f1, s_i1;
    if (threadIdx.x == 0) { s_other = 0; s_f1 = 0; s_i1 = 0; }
    __syncthreads();
    int lo = 0, lf = 0, li = 0;
    for (int i = threadIdx.x; i < 65536; i += blockDim.x) {
        unsigned v = w[i];
        if (v == 0u) continue;
        else if (v == 1u) li++;
        else if (v == 0x3F800000u) lf++;
        else lo++;
    }
    atomicAdd(&s_other, lo); atomicAdd(&s_f1, lf); atomicAdd(&s_i1, li);
    __syncthreads();
    if (threadIdx.x == 0) {
        int mode;
        if (s_other > 1024) mode = 0;
        else if (s_f1 >= s_i1) mode = 2;
        else mode = 1;
        g_mask_mode = mode;
    }
}

// Fused: noisy = where(mask,0,likes) -> fp16 padded  AND  column partial sums
// of likes (for popular). One pass over likes. grid (ceil(KPAD/256), 16).
__global__ void premask_popular_kernel(const float* __restrict__ likes,
                                       const void* __restrict__ mask,
                                       __half* __restrict__ noisy,
                                       float* __restrict__ part) {
    const int mode = g_mask_mode;
    const int col = blockIdx.x * 256 + threadIdx.x;
    if (col >= KPAD) return;
    const int r0 = blockIdx.y * 128;

    if (col >= NITEMS) {  // padding region: zero noisy, no popular
        const __half hz = __float2half_rn(0.f);
        for (int r = 0; r < 128; r++)
            noisy[(size_t)(r0 + r) * KPAD + col] = hz;
        return;
    }

    const unsigned char* m8 = (const unsigned char*)mask;
    const int*           mi = (const int*)mask;
    const float*         mf = (const float*)mask;

    float sum = 0.f;
    #pragma unroll 4
    for (int r = 0; r < 128; r++) {
        size_t e = (size_t)(r0 + r) * NITEMS + col;
        float v = likes[e];
        sum += v;
        bool drop;
        if (mode == 0)      drop = (m8[e] != 0);
        else if (mode == 1) drop = (mi[e] != 0);
        else                drop = (mf[e] != 0.f);
        noisy[(size_t)(r0 + r) * KPAD + col] = __float2half_rn(drop ? 0.f : v);
    }
    part[blockIdx.y * NITEMS + col] = sum;
}

__global__ void popular_reduce_kernel(const float* __restrict__ part,
                                      float* __restrict__ out_pop) {
    int i = blockIdx.x * 256 + threadIdx.x;
    if (i >= NITEMS) return;
    float s = 0.f;
    #pragma unroll
    for (int c = 0; c < 16; c++) s += part[c * NITEMS + i];
    out_pop[i] = s * (1.0f / (float)BATCH);
}

// per-row l2 normalize; emit fp16 normalized AND fp16 copy of E
__global__ void norm_half_kernel(const float* __restrict__ E,
                                 __half* __restrict__ Nrmh,
                                 __half* __restrict__ Eh) {
    int row = blockIdx.x;
    int t = threadIdx.x;   // 128 threads, EMB=512 -> one float4 each
    float4 v = reinterpret_cast<const float4*>(E + (size_t)row * EMB)[t];
    float ss = v.x * v.x + v.y * v.y + v.z * v.z + v.w * v.w;
    #pragma unroll
    for (int o = 16; o > 0; o >>= 1)
        ss += __shfl_xor_sync(0xFFFFFFFFu, ss, o);
    __shared__ float ws[4];
    if ((t & 31) == 0) ws[t >> 5] = ss;
    __syncthreads();
    float tot = ws[0] + ws[1] + ws[2] + ws[3];
    float inv = rsqrtf(fmaxf(tot, 1e-12f));
    __half2* eh = reinterpret_cast<__half2*>(Eh + (size_t)row * EMB + t * 4);
    eh[0] = __floats2half2_rn(v.x, v.y);
    eh[1] = __floats2half2_rn(v.z, v.w);
    __half2* nh = reinterpret_cast<__half2*>(Nrmh + (size_t)row * EMB + t * 4);
    nh[0] = __floats2half2_rn(v.x * inv, v.y * inv);
    nh[1] = __floats2half2_rn(v.z * inv, v.w * inv);
}

// f32 -> fp16 convert, contiguous, zero-padded beyond R*C (out has Rp*C elems)
__global__ void convert_pad_kernel(const float* __restrict__ in,
                                   __half* __restrict__ out,
                                   long validElems, long total8) {
    long i = (long)blockIdx.x * blockDim.x + threadIdx.x;
    if (i >= total8) return;
    long e = i * 8;
    __half2 h[4];
    if (e + 8 <= validElems) {
        float4 a = *reinterpret_cast<const float4*>(in + e);
        float4 b = *reinterpret_cast<const float4*>(in + e + 4);
        h[0] = __floats2half2_rn(a.x, a.y);
        h[1] = __floats2half2_rn(a.z, a.w);
        h[2] = __floats2half2_rn(b.x, b.y);
        h[3] = __floats2half2_rn(b.z, b.w);
    } else {
        h[0] = h[1] = h[2] = h[3] = __floats2half2_rn(0.f, 0.f);
    }
    __half2* dst = reinterpret_cast<__half2*>(out + e);
    dst[0] = h[0]; dst[1] = h[1]; dst[2] = h[2]; dst[3] = h[3];
}

// f32 [K][C] -> fp16 written into out[k][colOff + c] with row stride ldo
__global__ void convert_cols_kernel(const float* __restrict__ in,
                                    __half* __restrict__ out,
                                    int C, int ldo, int colOff, int total8) {
    int i = blockIdx.x * blockDim.x + threadIdx.x;
    if (i >= total8) return;
    long e = (long)i * 8;
    int k = (int)(e / C);
    int c = (int)(e - (long)k * C);
    float4 a = *reinterpret_cast<const float4*>(in + e);
    float4 b = *reinterpret_cast<const float4*>(in + e + 4);
    __half2* dst = reinterpret_cast<__half2*>(out + (size_t)k * ldo + colOff + c);
    dst[0] = __floats2half2_rn(a.x, a.y);
    dst[1] = __floats2half2_rn(a.z, a.w);
    dst[2] = __floats2half2_rn(b.x, b.y);
    dst[3] = __floats2half2_rn(b.z, b.w);
}

__global__ void concat2_kernel(const float* __restrict__ a,
                               const float* __restrict__ b,
                               float* __restrict__ o, int n) {
    int i = blockIdx.x * blockDim.x + threadIdx.x;
    if (i < n) o[i] = a[i];
    else if (i < 2 * n) o[i] = b[i - n];
}

// ---------------------------------------------------------------------------
// fp16 tensor-core GEMM.
//   TRANSB=false: C = act(A[M,K] @ Bt[N,K]^T + bias)   (B K-major, e.g. Nrm)
//   TRANSB=true : C = act(A[M,K] @ B[K,N] + bias)      (B row-major [K][N],
//                 loaded with ldmatrix.trans -- weights used as-is)
//   CTA tile 128x128, BK=64, 3-stage cp.async (96KB), 2 CTAs/SM, 8 warps.
// ---------------------------------------------------------------------------
enum { ACT_RELU = 0, ACT_SIG = 1, ACT_NEG = 2 };
#define BK 64
#define NSTAGE 3
#define ASZ 16384                 // A: 128 rows * 128B ; B: 64 rows * 256B (trans)
#define SSZ 32768                 // A + B per stage

template<int ACT, bool HAS_BIAS, bool OUT_HALF, bool TRANSB>
__global__ __launch_bounds__(256, 2)
void hmma_gemm(const __half* __restrict__ A, const __half* __restrict__ Bt,
               const float* __restrict__ bias, void* __restrict__ Cout,
               int M, int N, int K, int lda, int ldb) {
    extern __shared__ __align__(128) char smem[];
    const uint32_t sbase = smem_u32(smem);

    const int tid = threadIdx.x;
    const int lane = tid & 31, wid = tid >> 5;
    const int wm = (wid & 1) * 64;        // warp m offset in tile
    const int wn = (wid >> 1) * 32;       // warp n offset in tile
    const int m0 = blockIdx.x * 128;
    const int n0 = blockIdx.y * 128;
    const int nch = K / BK;

    float acc[4][4][4];
    #pragma unroll
    for (int i = 0; i < 4; i++)
        #pragma unroll
        for (int j = 0; j < 4; j++)
            #pragma unroll
            for (int q = 0; q < 4; q++) acc[i][j][q] = 0.f;

    // ---- stage loader ----
    auto load_stage = [&](int ch, int st) {
        const int k0 = ch * BK;
        const uint32_t sA = sbase + st * SSZ;
        const uint32_t sB = sA + ASZ;
        #pragma unroll
        for (int u = 0; u < 4; u++) {
            int idx = tid + u * 256;
            int r = idx >> 3, c = idx & 7;
            const __half* src = A + (size_t)(m0 + r) * lda + k0 + c * 8;
            cp16(sA + r * 128 + ((c ^ (r & 7)) << 4), src, 16);
        }
        if constexpr (!TRANSB) {
            #pragma unroll
            for (int u = 0; u < 4; u++) {
                int idx = tid + u * 256;
                int r = idx >> 3, c = idx & 7;
                int n = n0 + r;
                const __half* src = Bt + (size_t)n * ldb + k0 + c * 8;
                cp16(sB + r * 128 + ((c ^ (r & 7)) << 4), src, (n < N) ? 16 : 0);
            }
        } else {
            // B tile [BK=64 k-rows][128 n], 256B per k-row, per-128B-half swizzle
            #pragma unroll
            for (int u = 0; u < 4; u++) {
                int idx = tid + u * 256;
                int k = idx >> 4, c = idx & 15;
                const __half* src = Bt + (size_t)(k0 + k) * ldb + n0 + c * 8;
                uint32_t dst = sB + k * 256 + ((c >> 3) << 7)
                             + (((c & 7) ^ (k & 7)) << 4);
                cp16(dst, src, (n0 + c * 8 + 8 <= N) ? 16 : 0);
            }
        }
        CP_COMMIT();
    };

    // ldmatrix lane addressing
    const int aRow = wm + (lane & 15);
    const int aKsel = lane >> 4;
    const int swz = lane & 7;
    // non-trans B
    const int bRow = wn + ((lane >> 4) << 3) + (lane & 7);
    const int bKsel = (lane >> 3) & 1;
    // trans B: lane -> k row within k16, plus two n-octet byte offsets
    const int kLane = ((lane >> 3) & 1) * 8 + (lane & 7);
    int bOffT0 = 0, bOffT1 = 0;
    {
        int n0l = wn + ((lane >> 4) << 3);
        int c0 = n0l >> 3, c1 = (n0l + 16) >> 3;
        bOffT0 = ((c0 >> 3) << 7) + (((c0 & 7) ^ (lane & 7)) << 4);
        bOffT1 = ((c1 >> 3) << 7) + (((c1 & 7) ^ (lane & 7)) << 4);
    }

    load_stage(0, 0);
    load_stage(1, 1);

    for (int i = 0; i < nch; i++) {
        const int j = i + NSTAGE - 1;
        if (j < nch) load_stage(j, j % NSTAGE);
        else         CP_COMMIT();           // keep wait count aligned
        CP_WAIT(NSTAGE - 1);
        __syncthreads();

        const uint32_t sA = sbase + (i % NSTAGE) * SSZ;
        const uint32_t sB = sA + ASZ;
        #pragma unroll
        for (int kk = 0; kk < 4; kk++) {
            uint32_t a[4][4], b[2][4];
            const uint32_t aByte = ((2 * kk + aKsel) ^ swz) << 4;
            #pragma unroll
            for (int mf = 0; mf < 4; mf++)
                LDSM_X4(a[mf], sA + (aRow + 16 * mf) * 128 + aByte);
            if constexpr (!TRANSB) {
                const uint32_t bByte = ((2 * kk + bKsel) ^ swz) << 4;
                #pragma unroll
                for (int nf2 = 0; nf2 < 2; nf2++)
                    LDSM_X4(b[nf2], sB + (bRow + 16 * nf2) * 128 + bByte);
            } else {
                const uint32_t rowB = sB + (kk * 16 + kLane) * 256;
                LDSM_X4_T(b[0], rowB + bOffT0);
                LDSM_X4_T(b[1], rowB + bOffT1);
            }
            #pragma unroll
            for (int mf = 0; mf < 4; mf++)
                #pragma unroll
                for (int nf = 0; nf < 4; nf++)
                    mma16816(acc[mf][nf], a[mf],
                             b[nf >> 1][(nf & 1) * 2],
                             b[nf >> 1][(nf & 1) * 2 + 1]);
        }
        __syncthreads();
    }

    // ---- epilogue ----
    #pragma unroll
    for (int mf = 0; mf < 4; mf++) {
        const int row = m0 + wm + mf * 16 + (lane >> 2);
        #pragma unroll
        for (int nf = 0; nf < 4; nf++) {
            const int col = n0 + wn + nf * 8 + 2 * (lane & 3);
            if (col >= N) continue;
            float2 lo = make_float2(acc[mf][nf][0], acc[mf][nf][1]);
            float2 hi = make_float2(acc[mf][nf][2], acc[mf][nf][3]);
            if (HAS_BIAS) {
                float2 bb = *reinterpret_cast<const float2*>(bias + col);
                lo.x += bb.x; lo.y += bb.y;
                hi.x += bb.x; hi.y += bb.y;
            }
            if (ACT == ACT_RELU) {
                lo.x = fmaxf(lo.x, 0.f); lo.y = fmaxf(lo.y, 0.f);
                hi.x = fmaxf(hi.x, 0.f); hi.y = fmaxf(hi.y, 0.f);
            } else if (ACT == ACT_SIG) {
                lo.x = 1.f / (1.f + __expf(-lo.x));
                lo.y = 1.f / (1.f + __expf(-lo.y));
                hi.x = 1.f / (1.f + __expf(-hi.x));
                hi.y = 1.f / (1.f + __expf(-hi.y));
            } else {
                lo.x = -lo.x; lo.y = -lo.y;
                hi.x = -hi.x; hi.y = -hi.y;
            }
            if (OUT_HALF) {
                __half* C = (__half*)Cout;
                *reinterpret_cast<__half2*>(C + (size_t)row * N + col) =
                    __floats2half2_rn(lo.x, lo.y);
                *reinterpret_cast<__half2*>(C + (size_t)(row + 8) * N + col) =
                    __floats2half2_rn(hi.x, hi.y);
            } else {
                float* C = (float*)Cout;
                *reinterpret_cast<float2*>(C + (size_t)row * N + col) = lo;
                *reinterpret_cast<float2*>(C + (size_t)(row + 8) * N + col) = hi;
            }
        }
    }
}

// ---------------------------------------------------------------------------
// Launch (serial, single stream; gemm1 is the 6th launch for ncu -s 5 -c 1)
// ---------------------------------------------------------------------------
extern "C" void kernel_launch(void* const* d_in, const int* in_sizes, int n_in,
                              void* d_out, int out_size) {
    const float* likes  = (const float*)d_in[1];
    const void*  nmask  = d_in[2];
    const float* enc_w1 = (const float*)d_in[3];
    const float* enc_b1 = (const float*)d_in[4];
    const float* enc_w2 = (const float*)d_in[5];
    const float* enc_b2 = (const float*)d_in[6];
    const float* lk_w1  = (const float*)d_in[7];
    const float* lk_b1  = (const float*)d_in[8];
    const float* lk_w2  = (const float*)d_in[9];
    const float* lk_b2  = (const float*)d_in[10];
    const float* rc_w1  = (const float*)d_in[11];
    const float* rc_b1  = (const float*)d_in[12];
    const float* rc_w2  = (const float*)d_in[13];
    const float* rc_b2  = (const float*)d_in[14];

    float* out       = (float*)d_out;
    float* out_likes = out;
    float* out_sim   = out_likes + (size_t)BATCH * NITEMS;
    float* out_rec   = out_sim + (size_t)BATCH * BATCH;
    float* out_pop   = out_rec + (size_t)BATCH * NITEMS;

    __half *noisyh, *W1c, *W2c, *Wlr, *W4c, *W6c, *Hh, *Hh2, *Eh, *Nrmh;
    float *E, *part, *blr;
    cudaGetSymbolAddress((void**)&noisyh, g_noisyh);
    cudaGetSymbolAddress((void**)&W1c, g_W1c);
    cudaGetSymbolAddress((void**)&W2c, g_W2c);
    cudaGetSymbolAddress((void**)&Wlr, g_Wlr);
    cudaGetSymbolAddress((void**)&W4c, g_W4c);
    cudaGetSymbolAddress((void**)&W6c, g_W6c);
    cudaGetSymbolAddress((void**)&blr, g_blr);
    cudaGetSymbolAddress((void**)&Hh, g_Hh);
    cudaGetSymbolAddress((void**)&Hh2, g_Hh2);
    cudaGetSymbolAddress((void**)&E, g_E);
    cudaGetSymbolAddress((void**)&Eh, g_Eh);
    cudaGetSymbolAddress((void**)&Nrmh, g_Nrmh);
    cudaGetSymbolAddress((void**)&part, g_part);

    const int smem = NSTAGE * SSZ;  // 96KB
    cudaFuncSetAttribute(hmma_gemm<ACT_RELU, true, true, true>,
                         cudaFuncAttributeMaxDynamicSharedMemorySize, smem);
    cudaFuncSetAttribute(hmma_gemm<ACT_RELU, true, false, true>,
                         cudaFuncAttributeMaxDynamicSharedMemorySize, smem);
    cudaFuncSetAttribute(hmma_gemm<ACT_SIG, true, false, true>,
                         cudaFuncAttributeMaxDynamicSharedMemorySize, smem);
    cudaFuncSetAttribute(hmma_gemm<ACT_NEG, false, false, false>,
                         cudaFuncAttributeMaxDynamicSharedMemorySize, smem);

    // 1: mask probe
    probe_mask_kernel<<<1, 256>>>((const unsigned int*)nmask);
    // 2: fused denoise + popular partials
    premask_popular_kernel<<<dim3((KPAD + 255) / 256, 16), 256>>>(
        likes, nmask, noisyh, part);
    // 3: popular reduce
    popular_reduce_kernel<<<(NITEMS + 255) / 256, 256>>>(part, out_pop);
    // 4: convert enc_w1 [20000][1024] -> fp16 [20032][1024] (zero-pad rows)
    {
        long valid = (long)NITEMS * HID;
        long tot8 = (long)KPAD * HID / 8;
        convert_pad_kernel<<<(int)((tot8 + 255) / 256), 256>>>(
            enc_w1, W1c, valid, tot8);
    }
    // 5: convert enc_w2 [1024][512]
    {
        long tot8 = (long)HID * EMB / 8;
        convert_pad_kernel<<<(int)((tot8 + 255) / 256), 256>>>(
            enc_w2, W2c, (long)HID * EMB, tot8);
    }
    // 6: big encoder GEMM (profiled): Hh = relu(noisy @ enc_w1 + b1)
    hmma_gemm<ACT_RELU, true, true, true>
        <<<dim3(BATCH / 128, HID / 128), 256, smem>>>(
        noisyh, W1c, enc_b1, Hh, BATCH, HID, KPAD, KPAD, HID);

    // remaining converts
    {
        int tot8 = EMB * HID / 8;
        convert_cols_kernel<<<(tot8 + 255) / 256, 256>>>(
            lk_w1, Wlr, HID, 2 * HID, 0, tot8);
        convert_cols_kernel<<<(tot8 + 255) / 256, 256>>>(
            rc_w1, Wlr, HID, 2 * HID, HID, tot8);
    }
    concat2_kernel<<<(2 * HID + 255) / 256, 256>>>(lk_b1, rc_b1, blr, HID);
    {
        long tot8 = (long)HID * NITEMS / 8;
        convert_pad_kernel<<<(int)((tot8 + 255) / 256), 256>>>(
            lk_w2, W4c, (long)HID * NITEMS, tot8);
        convert_pad_kernel<<<(int)((tot8 + 255) / 256), 256>>>(
            rc_w2, W6c, (long)HID * NITEMS, tot8);
    }

    // encoder layer 2 + norm
    hmma_gemm<ACT_RELU, true, false, true>
        <<<dim3(BATCH / 128, EMB / 128), 256, smem>>>(
        Hh, W2c, enc_b2, E, BATCH, EMB, HID, HID, EMB);
    norm_half_kernel<<<BATCH, 128>>>(E, Nrmh, Eh);

    // user_sim = -(Nrm @ Nrm^T)   (K-major B path)
    hmma_gemm<ACT_NEG, false, false, false>
        <<<dim3(BATCH / 128, BATCH / 128), 256, smem>>>(
        Nrmh, Nrmh, nullptr, out_sim, BATCH, BATCH, EMB, EMB, EMB);

    // fused head hiddens: Hh2 = relu(Eh @ [lk_w1 | rc_w1] + [b|b])  [2048][2048]
    hmma_gemm<ACT_RELU, true, true, true>
        <<<dim3(BATCH / 128, (2 * HID) / 128), 256, smem>>>(
        Eh, Wlr, blr, Hh2, BATCH, 2 * HID, EMB, EMB, 2 * HID);

    // head outputs
    hmma_gemm<ACT_SIG, true, false, true>
        <<<dim3(BATCH / 128, (NITEMS + 127) / 128), 256, smem>>>(
        Hh2, W4c, lk_b2, out_likes, BATCH, NITEMS, HID, 2 * HID, NITEMS);
    hmma_gemm<ACT_SIG, true, false, true>
        <<<dim3(BATCH / 128, (NITEMS + 127) / 128), 256, smem>>>(
        Hh2 + HID, W6c, rc_b2, out_rec, BATCH, NITEMS, HID, 2 * HID, NITEMS);
}

// round 9
// speedup vs baseline: 1.1486x; 1.0074x over previous
#include <cuda_runtime.h>
#include <cuda_fp16.h>
#include <cstdint>

// Problem constants
#define BATCH  2048
#define NITEMS 20000
#define KPAD   20032   // NITEMS padded to multiple of 64
#define EMB    512
#define HID    1024    // 2*D

// ---------------------------------------------------------------------------
// Scratch (no allocations -> __device__ globals)
// Weights are CONVERTED (f32->fp16) keeping [K][N] row-major layout and
// consumed by the trans-B GEMM path -- no transposes needed.
// ---------------------------------------------------------------------------
__device__ __half g_noisyh[(size_t)BATCH * KPAD];    // masked likes fp16, padded
__device__ __half g_W1c[(size_t)KPAD * HID];         // enc_w1 fp16 [20032][1024]
__device__ __half g_W2c[(size_t)HID * EMB];          // enc_w2 fp16 [1024][512]
__device__ __half g_Wlr[(size_t)EMB * (2 * HID)];    // [512][2048] = lk_w1 ++ rc_w1
__device__ __half g_W4c[(size_t)HID * NITEMS];       // lk_w2 fp16 [1024][20000]
__device__ __half g_W6c[(size_t)HID * NITEMS];       // rc_w2 fp16 [1024][20000]
__device__ float  g_blr[2 * HID];                    // lk_b1 ++ rc_b1
__device__ __half g_Hh[(size_t)BATCH * HID];         // encoder hidden fp16
__device__ __half g_Hh2[(size_t)BATCH * 2 * HID];    // fused head hiddens fp16
__device__ float  g_E[(size_t)BATCH * EMB];          // embed f32
__device__ __half g_Eh[(size_t)BATCH * EMB];         // embed fp16
__device__ __half g_Nrmh[(size_t)BATCH * EMB];       // normalized fp16
__device__ float  g_part[16 * NITEMS];
__device__ int    g_mask_mode;  // 0=u8, 1=i32, 2=f32

// ---------------------------------------------------------------------------
// PTX helpers (arch-generic sm_80-era instructions)
// ---------------------------------------------------------------------------
__device__ __forceinline__ uint32_t smem_u32(const void* p) {
    uint32_t a;
    asm("{ .reg .u64 t; cvta.to.shared.u64 t, %1; cvt.u32.u64 %0, t; }"
        : "=r"(a) : "l"(p));
    return a;
}
__device__ __forceinline__ void cp16(uint32_t dst, const void* src, int sz) {
    asm volatile("cp.async.cg.shared.global [%0], [%1], 16, %2;"
        :: "r"(dst), "l"(src), "r"(sz));
}
#define CP_COMMIT() asm volatile("cp.async.commit_group;" ::: "memory")
#define CP_WAIT(n)  asm volatile("cp.async.wait_group %0;" :: "n"(n) : "memory")

#define LDSM_X4(r, addr) \
    asm volatile("ldmatrix.sync.aligned.m8n8.x4.shared.b16 {%0,%1,%2,%3}, [%4];" \
        : "=r"((r)[0]), "=r"((r)[1]), "=r"((r)[2]), "=r"((r)[3]) : "r"(addr))

#define LDSM_X4_T(r, addr) \
    asm volatile("ldmatrix.sync.aligned.m8n8.x4.trans.shared.b16 {%0,%1,%2,%3}, [%4];" \
        : "=r"((r)[0]), "=r"((r)[1]), "=r"((r)[2]), "=r"((r)[3]) : "r"(addr))

__device__ __forceinline__ void mma16816(float* d, const uint32_t* a,
                                         uint32_t b0, uint32_t b1) {
    asm volatile(
        "mma.sync.aligned.m16n8k16.row.col.f32.f16.f16.f32 "
        "{%0,%1,%2,%3}, {%4,%5,%6,%7}, {%8,%9}, {%0,%1,%2,%3};"
        : "+f"(d[0]), "+f"(d[1]), "+f"(d[2]), "+f"(d[3])
        : "r"(a[0]), "r"(a[1]), "r"(a[2]), "r"(a[3]), "r"(b0), "r"(b1));
}

// ---------------------------------------------------------------------------
// Small kernels
// ---------------------------------------------------------------------------
__global__ void probe_mask_kernel(const unsigned int* __restrict__ w) {
    __shared__ int s_other, s_f1, s_i1;
    if (threadIdx.x == 0) { s_other = 0; s_f1 = 0; s_i1 = 0; }
    __syncthreads();
    int lo = 0, lf = 0, li = 0;
    for (int i = threadIdx.x; i < 65536; i += blockDim.x) {
        unsigned v = w[i];
        if (v == 0u) continue;
        else if (v == 1u) li++;
        else if (v == 0x3F800000u) lf++;
        else lo++;
    }
    atomicAdd(&s_other, lo); atomicAdd(&s_f1, lf); atomicAdd(&s_i1, li);
    __syncthreads();
    if (threadIdx.x == 0) {
        int mode;
        if (s_other > 1024) mode = 0;
        else if (s_f1 >= s_i1) mode = 2;
        else mode = 1;
        g_mask_mode = mode;
    }
}

// Fused: noisy = where(mask,0,likes) -> fp16 padded  AND  column partial sums
// of likes (for popular). One pass over likes. grid (ceil(KPAD/256), 16).
__global__ void premask_popular_kernel(const float* __restrict__ likes,
                                       const void* __restrict__ mask,
                                       __half* __restrict__ noisy,
                                       float* __restrict__ part) {
    const int mode = g_mask_mode;
    const int col = blockIdx.x * 256 + threadIdx.x;
    if (col >= KPAD) return;
    const int r0 = blockIdx.y * 128;

    if (col >= NITEMS) {  // padding region: zero noisy, no popular
        const __half hz = __float2half_rn(0.f);
        for (int r = 0; r < 128; r++)
            noisy[(size_t)(r0 + r) * KPAD + col] = hz;
        return;
    }

    const unsigned char* m8 = (const unsigned char*)mask;
    const int*           mi = (const int*)mask;
    const float*         mf = (const float*)mask;

    float sum = 0.f;
    #pragma unroll 4
    for (int r = 0; r < 128; r++) {
        size_t e = (size_t)(r0 + r) * NITEMS + col;
        float v = likes[e];
        sum += v;
        bool drop;
        if (mode == 0)      drop = (m8[e] != 0);
        else if (mode == 1) drop = (mi[e] != 0);
        else                drop = (mf[e] != 0.f);
        noisy[(size_t)(r0 + r) * KPAD + col] = __float2half_rn(drop ? 0.f : v);
    }
    part[blockIdx.y * NITEMS + col] = sum;
}

__global__ void popular_reduce_kernel(const float* __restrict__ part,
                                      float* __restrict__ out_pop) {
    int i = blockIdx.x * 256 + threadIdx.x;
    if (i >= NITEMS) return;
    float s = 0.f;
    #pragma unroll
    for (int c = 0; c < 16; c++) s += part[c * NITEMS + i];
    out_pop[i] = s * (1.0f / (float)BATCH);
}

// per-row l2 normalize; emit fp16 normalized AND fp16 copy of E
__global__ void norm_half_kernel(const float* __restrict__ E,
                                 __half* __restrict__ Nrmh,
                                 __half* __restrict__ Eh) {
    int row = blockIdx.x;
    int t = threadIdx.x;   // 128 threads, EMB=512 -> one float4 each
    float4 v = reinterpret_cast<const float4*>(E + (size_t)row * EMB)[t];
    float ss = v.x * v.x + v.y * v.y + v.z * v.z + v.w * v.w;
    #pragma unroll
    for (int o = 16; o > 0; o >>= 1)
        ss += __shfl_xor_sync(0xFFFFFFFFu, ss, o);
    __shared__ float ws[4];
    if ((t & 31) == 0) ws[t >> 5] = ss;
    __syncthreads();
    float tot = ws[0] + ws[1] + ws[2] + ws[3];
    float inv = rsqrtf(fmaxf(tot, 1e-12f));
    __half2* eh = reinterpret_cast<__half2*>(Eh + (size_t)row * EMB + t * 4);
    eh[0] = __floats2half2_rn(v.x, v.y);
    eh[1] = __floats2half2_rn(v.z, v.w);
    __half2* nh = reinterpret_cast<__half2*>(Nrmh + (size_t)row * EMB + t * 4);
    nh[0] = __floats2half2_rn(v.x * inv, v.y * inv);
    nh[1] = __floats2half2_rn(v.z * inv, v.w * inv);
}

// f32 -> fp16 convert, contiguous, zero-padded beyond validElems
__global__ void convert_pad_kernel(const float* __restrict__ in,
                                   __half* __restrict__ out,
                                   long validElems, long total8) {
    long i = (long)blockIdx.x * blockDim.x + threadIdx.x;
    if (i >= total8) return;
    long e = i * 8;
    __half2 h[4];
    if (e + 8 <= validElems) {
        float4 a = *reinterpret_cast<const float4*>(in + e);
        float4 b = *reinterpret_cast<const float4*>(in + e + 4);
        h[0] = __floats2half2_rn(a.x, a.y);
        h[1] = __floats2half2_rn(a.z, a.w);
        h[2] = __floats2half2_rn(b.x, b.y);
        h[3] = __floats2half2_rn(b.z, b.w);
    } else {
        h[0] = h[1] = h[2] = h[3] = __floats2half2_rn(0.f, 0.f);
    }
    __half2* dst = reinterpret_cast<__half2*>(out + e);
    dst[0] = h[0]; dst[1] = h[1]; dst[2] = h[2]; dst[3] = h[3];
}

// f32 [K][C] -> fp16 written into out[k][colOff + c] with row stride ldo
__global__ void convert_cols_kernel(const float* __restrict__ in,
                                    __half* __restrict__ out,
                                    int C, int ldo, int colOff, int total8) {
    int i = blockIdx.x * blockDim.x + threadIdx.x;
    if (i >= total8) return;
    long e = (long)i * 8;
    int k = (int)(e / C);
    int c = (int)(e - (long)k * C);
    float4 a = *reinterpret_cast<const float4*>(in + e);
    float4 b = *reinterpret_cast<const float4*>(in + e + 4);
    __half2* dst = reinterpret_cast<__half2*>(out + (size_t)k * ldo + colOff + c);
    dst[0] = __floats2half2_rn(a.x, a.y);
    dst[1] = __floats2half2_rn(a.z, a.w);
    dst[2] = __floats2half2_rn(b.x, b.y);
    dst[3] = __floats2half2_rn(b.z, b.w);
}

__global__ void concat2_kernel(const float* __restrict__ a,
                               const float* __restrict__ b,
                               float* __restrict__ o, int n) {
    int i = blockIdx.x * blockDim.x + threadIdx.x;
    if (i < n) o[i] = a[i];
    else if (i < 2 * n) o[i] = b[i - n];
}

// ---------------------------------------------------------------------------
// fp16 tensor-core GEMM.
//   TRANSB=false: C = act(A[M,K] @ Bt[N,K]^T + bias)   (B K-major)
//   TRANSB=true : C = act(A[M,K] @ B[K,N] + bias)      (B row-major [K][N])
//   Dual mode: CTAs with blockIdx.y >= nSplit use the second pointer set
//   (A2/B2/bias2/C2) -- merges two same-shape GEMMs into one launch to kill
//   wave quantization. Pass a huge nSplit for single GEMMs.
//   CTA tile 128x128, BK=64, 3-stage cp.async (96KB), 2 CTAs/SM, 8 warps.
// ---------------------------------------------------------------------------
enum { ACT_RELU = 0, ACT_SIG = 1, ACT_NEG = 2 };
#define BK 64
#define NSTAGE 3
#define ASZ 16384                 // A: 128 rows * 128B ; B(trans): 64 rows * 256B
#define SSZ 32768                 // A + B per stage

template<int ACT, bool HAS_BIAS, bool OUT_HALF, bool TRANSB>
__global__ __launch_bounds__(256, 2)
void hmma_gemm(const __half* __restrict__ Ap, const __half* __restrict__ Bp,
               const float* __restrict__ biasp, void* __restrict__ Coutp,
               int M, int N, int K, int lda, int ldb,
               const __half* A2, const __half* B2,
               const float* bias2, void* Cout2, int nSplit) {
    extern __shared__ __align__(128) char smem[];
    const uint32_t sbase = smem_u32(smem);

    const __half* A   = Ap;
    const __half* Bt  = Bp;
    const float* bias = biasp;
    void* Cout        = Coutp;
    int by = blockIdx.y;
    if (by >= nSplit) {
        by -= nSplit;
        A = A2; Bt = B2; bias = bias2; Cout = Cout2;
    }

    const int tid = threadIdx.x;
    const int lane = tid & 31, wid = tid >> 5;
    const int wm = (wid & 1) * 64;        // warp m offset in tile
    const int wn = (wid >> 1) * 32;       // warp n offset in tile
    const int m0 = blockIdx.x * 128;
    const int n0 = by * 128;
    const int nch = K / BK;

    float acc[4][4][4];
    #pragma unroll
    for (int i = 0; i < 4; i++)
        #pragma unroll
        for (int j = 0; j < 4; j++)
            #pragma unroll
            for (int q = 0; q < 4; q++) acc[i][j][q] = 0.f;

    // ---- stage loader ----
    auto load_stage = [&](int ch, int st) {
        const int k0 = ch * BK;
        const uint32_t sA = sbase + st * SSZ;
        const uint32_t sB = sA + ASZ;
        #pragma unroll
        for (int u = 0; u < 4; u++) {
            int idx = tid + u * 256;
            int r = idx >> 3, c = idx & 7;
            const __half* src = A + (size_t)(m0 + r) * lda + k0 + c * 8;
            cp16(sA + r * 128 + ((c ^ (r & 7)) << 4), src, 16);
        }
        if constexpr (!TRANSB) {
            #pragma unroll
            for (int u = 0; u < 4; u++) {
                int idx = tid + u * 256;
                int r = idx >> 3, c = idx & 7;
                int n = n0 + r;
                const __half* src = Bt + (size_t)n * ldb + k0 + c * 8;
                cp16(sB + r * 128 + ((c ^ (r & 7)) << 4), src, (n < N) ? 16 : 0);
            }
        } else {
            // B tile [BK=64 k-rows][128 n], 256B per k-row, per-128B-half swizzle
            #pragma unroll
            for (int u = 0; u < 4; u++) {
                int idx = tid + u * 256;
                int k = idx >> 4, c = idx & 15;
                const __half* src = Bt + (size_t)(k0 + k) * ldb + n0 + c * 8;
                uint32_t dst = sB + k * 256 + ((c >> 3) << 7)
                             + (((c & 7) ^ (k & 7)) << 4);
                cp16(dst, src, (n0 + c * 8 + 8 <= N) ? 16 : 0);
            }
        }
        CP_COMMIT();
    };

    // ldmatrix lane addressing
    const int aRow = wm + (lane & 15);
    const int aKsel = lane >> 4;
    const int swz = lane & 7;
    // non-trans B
    const int bRow = wn + ((lane >> 4) << 3) + (lane & 7);
    const int bKsel = (lane >> 3) & 1;
    // trans B: lane -> k row within k16, plus two n-octet byte offsets
    const int kLane = ((lane >> 3) & 1) * 8 + (lane & 7);
    int bOffT0 = 0, bOffT1 = 0;
    {
        int n0l = wn + ((lane >> 4) << 3);
        int c0 = n0l >> 3, c1 = (n0l + 16) >> 3;
        bOffT0 = ((c0 >> 3) << 7) + (((c0 & 7) ^ (lane & 7)) << 4);
        bOffT1 = ((c1 >> 3) << 7) + (((c1 & 7) ^ (lane & 7)) << 4);
    }

    load_stage(0, 0);
    load_stage(1, 1);

    for (int i = 0; i < nch; i++) {
        const int j = i + NSTAGE - 1;
        if (j < nch) load_stage(j, j % NSTAGE);
        else         CP_COMMIT();           // keep wait count aligned
        CP_WAIT(NSTAGE - 1);
        __syncthreads();

        const uint32_t sA = sbase + (i % NSTAGE) * SSZ;
        const uint32_t sB = sA + ASZ;
        #pragma unroll
        for (int kk = 0; kk < 4; kk++) {
            uint32_t a[4][4], b[2][4];
            const uint32_t aByte = ((2 * kk + aKsel) ^ swz) << 4;
            #pragma unroll
            for (int mf = 0; mf < 4; mf++)
                LDSM_X4(a[mf], sA + (aRow + 16 * mf) * 128 + aByte);
            if constexpr (!TRANSB) {
                const uint32_t bByte = ((2 * kk + bKsel) ^ swz) << 4;
                #pragma unroll
                for (int nf2 = 0; nf2 < 2; nf2++)
                    LDSM_X4(b[nf2], sB + (bRow + 16 * nf2) * 128 + bByte);
            } else {
                const uint32_t rowB = sB + (kk * 16 + kLane) * 256;
                LDSM_X4_T(b[0], rowB + bOffT0);
                LDSM_X4_T(b[1], rowB + bOffT1);
            }
            #pragma unroll
            for (int mf = 0; mf < 4; mf++)
                #pragma unroll
                for (int nf = 0; nf < 4; nf++)
                    mma16816(acc[mf][nf], a[mf],
                             b[nf >> 1][(nf & 1) * 2],
                             b[nf >> 1][(nf & 1) * 2 + 1]);
        }
        __syncthreads();
    }

    // ---- epilogue ----
    #pragma unroll
    for (int mf = 0; mf < 4; mf++) {
        const int row = m0 + wm + mf * 16 + (lane >> 2);
        #pragma unroll
        for (int nf = 0; nf < 4; nf++) {
            const int col = n0 + wn + nf * 8 + 2 * (lane & 3);
            if (col >= N) continue;
            float2 lo = make_float2(acc[mf][nf][0], acc[mf][nf][1]);
            float2 hi = make_float2(acc[mf][nf][2], acc[mf][nf][3]);
            if (HAS_BIAS) {
                float2 bb = *reinterpret_cast<const float2*>(bias + col);
                lo.x += bb.x; lo.y += bb.y;
                hi.x += bb.x; hi.y += bb.y;
            }
            if (ACT == ACT_RELU) {
                lo.x = fmaxf(lo.x, 0.f); lo.y = fmaxf(lo.y, 0.f);
                hi.x = fmaxf(hi.x, 0.f); hi.y = fmaxf(hi.y, 0.f);
            } else if (ACT == ACT_SIG) {
                lo.x = 1.f / (1.f + __expf(-lo.x));
                lo.y = 1.f / (1.f + __expf(-lo.y));
                hi.x = 1.f / (1.f + __expf(-hi.x));
                hi.y = 1.f / (1.f + __expf(-hi.y));
            } else {
                lo.x = -lo.x; lo.y = -lo.y;
                hi.x = -hi.x; hi.y = -hi.y;
            }
            if (OUT_HALF) {
                __half* C = (__half*)Cout;
                *reinterpret_cast<__half2*>(C + (size_t)row * N + col) =
                    __floats2half2_rn(lo.x, lo.y);
                *reinterpret_cast<__half2*>(C + (size_t)(row + 8) * N + col) =
                    __floats2half2_rn(hi.x, hi.y);
            } else {
                float* C = (float*)Cout;
                *reinterpret_cast<float2*>(C + (size_t)row * N + col) = lo;
                *reinterpret_cast<float2*>(C + (size_t)(row + 8) * N + col) = hi;
            }
        }
    }
}

#define NO_DUAL nullptr, nullptr, nullptr, nullptr, 0x40000000

// ---------------------------------------------------------------------------
// Launch (serial; gemm1 is the 4th launch so ncu profiles it)
// ---------------------------------------------------------------------------
extern "C" void kernel_launch(void* const* d_in, const int* in_sizes, int n_in,
                              void* d_out, int out_size) {
    const float* likes  = (const float*)d_in[1];
    const void*  nmask  = d_in[2];
    const float* enc_w1 = (const float*)d_in[3];
    const float* enc_b1 = (const float*)d_in[4];
    const float* enc_w2 = (const float*)d_in[5];
    const float* enc_b2 = (const float*)d_in[6];
    const float* lk_w1  = (const float*)d_in[7];
    const float* lk_b1  = (const float*)d_in[8];
    const float* lk_w2  = (const float*)d_in[9];
    const float* lk_b2  = (const float*)d_in[10];
    const float* rc_w1  = (const float*)d_in[11];
    const float* rc_b1  = (const float*)d_in[12];
    const float* rc_w2  = (const float*)d_in[13];
    const float* rc_b2  = (const float*)d_in[14];

    float* out       = (float*)d_out;
    float* out_likes = out;
    float* out_sim   = out_likes + (size_t)BATCH * NITEMS;
    float* out_rec   = out_sim + (size_t)BATCH * BATCH;
    float* out_pop   = out_rec + (size_t)BATCH * NITEMS;

    __half *noisyh, *W1c, *W2c, *Wlr, *W4c, *W6c, *Hh, *Hh2, *Eh, *Nrmh;
    float *E, *part, *blr;
    cudaGetSymbolAddress((void**)&noisyh, g_noisyh);
    cudaGetSymbolAddress((void**)&W1c, g_W1c);
    cudaGetSymbolAddress((void**)&W2c, g_W2c);
    cudaGetSymbolAddress((void**)&Wlr, g_Wlr);
    cudaGetSymbolAddress((void**)&W4c, g_W4c);
    cudaGetSymbolAddress((void**)&W6c, g_W6c);
    cudaGetSymbolAddress((void**)&blr, g_blr);
    cudaGetSymbolAddress((void**)&Hh, g_Hh);
    cudaGetSymbolAddress((void**)&Hh2, g_Hh2);
    cudaGetSymbolAddress((void**)&E, g_E);
    cudaGetSymbolAddress((void**)&Eh, g_Eh);
    cudaGetSymbolAddress((void**)&Nrmh, g_Nrmh);
    cudaGetSymbolAddress((void**)&part, g_part);

    const int smem = NSTAGE * SSZ;  // 96KB
    cudaFuncSetAttribute(hmma_gemm<ACT_RELU, true, true, true>,
                         cudaFuncAttributeMaxDynamicSharedMemorySize, smem);
    cudaFuncSetAttribute(hmma_gemm<ACT_RELU, true, false, true>,
                         cudaFuncAttributeMaxDynamicSharedMemorySize, smem);
    cudaFuncSetAttribute(hmma_gemm<ACT_SIG, true, false, true>,
                         cudaFuncAttributeMaxDynamicSharedMemorySize, smem);
    cudaFuncSetAttribute(hmma_gemm<ACT_NEG, false, false, false>,
                         cudaFuncAttributeMaxDynamicSharedMemorySize, smem);

    // 1: mask probe
    probe_mask_kernel<<<1, 256>>>((const unsigned int*)nmask);
    // 2: fused denoise + popular partials
    premask_popular_kernel<<<dim3((KPAD + 255) / 256, 16), 256>>>(
        likes, nmask, noisyh, part);
    // 3: convert enc_w1 [20000][1024] -> fp16 [20032][1024] (zero-pad rows)
    {
        long valid = (long)NITEMS * HID;
        long tot8 = (long)KPAD * HID / 8;
        convert_pad_kernel<<<(int)((tot8 + 255) / 256), 256>>>(
            enc_w1, W1c, valid, tot8);
    }
    // 4: big encoder GEMM (profiled): Hh = relu(noisy @ enc_w1 + b1)
    hmma_gemm<ACT_RELU, true, true, true>
        <<<dim3(BATCH / 128, HID / 128), 256, smem>>>(
        noisyh, W1c, enc_b1, Hh, BATCH, HID, KPAD, KPAD, HID, NO_DUAL);

    // popular reduce + remaining converts
    popular_reduce_kernel<<<(NITEMS + 255) / 256, 256>>>(part, out_pop);
    {
        long tot8 = (long)HID * EMB / 8;
        convert_pad_kernel<<<(int)((tot8 + 255) / 256), 256>>>(
            enc_w2, W2c, (long)HID * EMB, tot8);
    }
    {
        int tot8 = EMB * HID / 8;
        convert_cols_kernel<<<(tot8 + 255) / 256, 256>>>(
            lk_w1, Wlr, HID, 2 * HID, 0, tot8);
        convert_cols_kernel<<<(tot8 + 255) / 256, 256>>>(
            rc_w1, Wlr, HID, 2 * HID, HID, tot8);
    }
    concat2_kernel<<<(2 * HID + 255) / 256, 256>>>(lk_b1, rc_b1, blr, HID);
    {
        long tot8 = (long)HID * NITEMS / 8;
        convert_pad_kernel<<<(int)((tot8 + 255) / 256), 256>>>(
            lk_w2, W4c, (long)HID * NITEMS, tot8);
        convert_pad_kernel<<<(int)((tot8 + 255) / 256), 256>>>(
            rc_w2, W6c, (long)HID * NITEMS, tot8);
    }

    // encoder layer 2 + norm
    hmma_gemm<ACT_RELU, true, false, true>
        <<<dim3(BATCH / 128, EMB / 128), 256, smem>>>(
        Hh, W2c, enc_b2, E, BATCH, EMB, HID, HID, EMB, NO_DUAL);
    norm_half_kernel<<<BATCH, 128>>>(E, Nrmh, Eh);

    // user_sim = -(Nrm @ Nrm^T)   (K-major B path)
    hmma_gemm<ACT_NEG, false, false, false>
        <<<dim3(BATCH / 128, BATCH / 128), 256, smem>>>(
        Nrmh, Nrmh, nullptr, out_sim, BATCH, BATCH, EMB, EMB, EMB, NO_DUAL);

    // fused head hiddens: Hh2 = relu(Eh @ [lk_w1 | rc_w1] + [b|b])  [2048][2048]
    hmma_gemm<ACT_RELU, true, true, true>
        <<<dim3(BATCH / 128, (2 * HID) / 128), 256, smem>>>(
        Eh, Wlr, blr, Hh2, BATCH, 2 * HID, EMB, EMB, 2 * HID, NO_DUAL);

    // BOTH head outputs in ONE launch: y-tiles [0,157) = likes head,
    // [157,314) = rec head. 5024 CTAs = 16.97 waves (vs 2 x 8.49 -> 2 x 9).
    const int nTiles = (NITEMS + 127) / 128;  // 157
    hmma_gemm<ACT_SIG, true, false, true>
        <<<dim3(BATCH / 128, 2 * nTiles), 256, smem>>>(
        Hh2, W4c, lk_b2, out_likes, BATCH, NITEMS, HID, 2 * HID, NITEMS,
        Hh2 + HID, W6c, rc_b2, out_rec, nTiles);
}

// round 10
// speedup vs baseline: 1.1703x; 1.0189x over previous
#include <cuda_runtime.h>
#include <cuda_fp16.h>
#include <cstdint>

// Problem constants
#define BATCH  2048
#define NITEMS 20000
#define KPAD   20096   // NITEMS padded to 2 x 10048 (157 x 64 per K-split)
#define KHALF  10048
#define EMB    512
#define HID    1024    // 2*D

// ---------------------------------------------------------------------------
// Scratch (no allocations -> __device__ globals)
// ---------------------------------------------------------------------------
__device__ __half g_noisyh[(size_t)BATCH * KPAD];    // masked likes fp16, padded
__device__ __half g_W1c[(size_t)KPAD * HID];         // enc_w1 fp16 [20096][1024]
__device__ __half g_W2c[(size_t)HID * EMB];          // enc_w2 fp16 [1024][512]
__device__ __half g_Wlr[(size_t)EMB * (2 * HID)];    // [512][2048] = lk_w1 ++ rc_w1
__device__ __half g_W4c[(size_t)HID * NITEMS];       // lk_w2 fp16 [1024][20000]
__device__ __half g_W6c[(size_t)HID * NITEMS];       // rc_w2 fp16 [1024][20000]
__device__ float  g_blr[2 * HID];                    // lk_b1 ++ rc_b1
__device__ float  g_psum[2 * (size_t)BATCH * HID];   // split-K partials (f32)
__device__ __half g_Hh[(size_t)BATCH * HID];         // encoder hidden fp16
__device__ __half g_Hh2[(size_t)BATCH * 2 * HID];    // fused head hiddens fp16
__device__ float  g_E[(size_t)BATCH * EMB];          // embed f32
__device__ __half g_Eh[(size_t)BATCH * EMB];         // embed fp16
__device__ __half g_Nrmh[(size_t)BATCH * EMB];       // normalized fp16
__device__ float  g_part[16 * NITEMS];
__device__ int    g_mask_mode;  // 0=u8, 1=i32, 2=f32

// ---------------------------------------------------------------------------
// PTX helpers (arch-generic sm_80-era instructions)
// ---------------------------------------------------------------------------
__device__ __forceinline__ uint32_t smem_u32(const void* p) {
    uint32_t a;
    asm("{ .reg .u64 t; cvta.to.shared.u64 t, %1; cvt.u32.u64 %0, t; }"
        : "=r"(a) : "l"(p));
    return a;
}
__device__ __forceinline__ void cp16(uint32_t dst, const void* src, int sz) {
    asm volatile("cp.async.cg.shared.global [%0], [%1], 16, %2;"
        :: "r"(dst), "l"(src), "r"(sz));
}
#define CP_COMMIT() asm volatile("cp.async.commit_group;" ::: "memory")
#define CP_WAIT(n)  asm volatile("cp.async.wait_group %0;" :: "n"(n) : "memory")

#define LDSM_X4(r, addr) \
    asm volatile("ldmatrix.sync.aligned.m8n8.x4.shared.b16 {%0,%1,%2,%3}, [%4];" \
        : "=r"((r)[0]), "=r"((r)[1]), "=r"((r)[2]), "=r"((r)[3]) : "r"(addr))

#define LDSM_X4_T(r, addr) \
    asm volatile("ldmatrix.sync.aligned.m8n8.x4.trans.shared.b16 {%0,%1,%2,%3}, [%4];" \
        : "=r"((r)[0]), "=r"((r)[1]), "=r"((r)[2]), "=r"((r)[3]) : "r"(addr))

__device__ __forceinline__ void mma16816(float* d, const uint32_t* a,
                                         uint32_t b0, uint32_t b1) {
    asm volatile(
        "mma.sync.aligned.m16n8k16.row.col.f32.f16.f16.f32 "
        "{%0,%1,%2,%3}, {%4,%5,%6,%7}, {%8,%9}, {%0,%1,%2,%3};"
        : "+f"(d[0]), "+f"(d[1]), "+f"(d[2]), "+f"(d[3])
        : "r"(a[0]), "r"(a[1]), "r"(a[2]), "r"(a[3]), "r"(b0), "r"(b1));
}

// ---------------------------------------------------------------------------
// Small kernels
// ---------------------------------------------------------------------------
__global__ void probe_mask_kernel(const unsigned int* __restrict__ w) {
    __shared__ int s_other, s_f1, s_i1;
    if (threadIdx.x == 0) { s_other = 0; s_f1 = 0; s_i1 = 0; }
    __syncthreads();
    int lo = 0, lf = 0, li = 0;
    for (int i = threadIdx.x; i < 65536; i += blockDim.x) {
        unsigned v = w[i];
        if (v == 0u) continue;
        else if (v == 1u) li++;
        else if (v == 0x3F800000u) lf++;
        else lo++;
    }
    atomicAdd(&s_other, lo); atomicAdd(&s_f1, lf); atomicAdd(&s_i1, li);
    __syncthreads();
    if (threadIdx.x == 0) {
        int mode;
        if (s_other > 1024) mode = 0;
        else if (s_f1 >= s_i1) mode = 2;
        else mode = 1;
        g_mask_mode = mode;
    }
}

// Fused: noisy = where(mask,0,likes) -> fp16 padded  AND  column partial sums
// of likes (for popular). One pass over likes. grid (ceil(KPAD/256), 16).
__global__ void premask_popular_kernel(const float* __restrict__ likes,
                                       const void* __restrict__ mask,
                                       __half* __restrict__ noisy,
                                       float* __restrict__ part) {
    const int mode = g_mask_mode;
    const int col = blockIdx.x * 256 + threadIdx.x;
    if (col >= KPAD) return;
    const int r0 = blockIdx.y * 128;

    if (col >= NITEMS) {  // padding region: zero noisy, no popular
        const __half hz = __float2half_rn(0.f);
        for (int r = 0; r < 128; r++)
            noisy[(size_t)(r0 + r) * KPAD + col] = hz;
        return;
    }

    const unsigned char* m8 = (const unsigned char*)mask;
    const int*           mi = (const int*)mask;
    const float*         mf = (const float*)mask;

    float sum = 0.f;
    #pragma unroll 4
    for (int r = 0; r < 128; r++) {
        size_t e = (size_t)(r0 + r) * NITEMS + col;
        float v = likes[e];
        sum += v;
        bool drop;
        if (mode == 0)      drop = (m8[e] != 0);
        else if (mode == 1) drop = (mi[e] != 0);
        else                drop = (mf[e] != 0.f);
        noisy[(size_t)(r0 + r) * KPAD + col] = __float2half_rn(drop ? 0.f : v);
    }
    part[blockIdx.y * NITEMS + col] = sum;
}

__global__ void popular_reduce_kernel(const float* __restrict__ part,
                                      float* __restrict__ out_pop) {
    int i = blockIdx.x * 256 + threadIdx.x;
    if (i >= NITEMS) return;
    float s = 0.f;
    #pragma unroll
    for (int c = 0; c < 16; c++) s += part[c * NITEMS + i];
    out_pop[i] = s * (1.0f / (float)BATCH);
}

// combine split-K partials: Hh = fp16(relu(p0 + p1 + bias))
__global__ void combine_splitk_kernel(const float* __restrict__ p,
                                      const float* __restrict__ bias,
                                      __half* __restrict__ out) {
    const size_t MN = (size_t)BATCH * HID;
    size_t e = ((size_t)blockIdx.x * 256 + threadIdx.x) * 4;
    if (e >= MN) return;
    int col = (int)(e & (HID - 1));
    float4 a = *reinterpret_cast<const float4*>(p + e);
    float4 b = *reinterpret_cast<const float4*>(p + MN + e);
    float4 bb = *reinterpret_cast<const float4*>(bias + col);
    float x0 = fmaxf(a.x + b.x + bb.x, 0.f);
    float x1 = fmaxf(a.y + b.y + bb.y, 0.f);
    float x2 = fmaxf(a.z + b.z + bb.z, 0.f);
    float x3 = fmaxf(a.w + b.w + bb.w, 0.f);
    __half2* dst = reinterpret_cast<__half2*>(out + e);
    dst[0] = __floats2half2_rn(x0, x1);
    dst[1] = __floats2half2_rn(x2, x3);
}

// per-row l2 normalize; emit fp16 normalized AND fp16 copy of E
__global__ void norm_half_kernel(const float* __restrict__ E,
                                 __half* __restrict__ Nrmh,
                                 __half* __restrict__ Eh) {
    int row = blockIdx.x;
    int t = threadIdx.x;   // 128 threads, EMB=512 -> one float4 each
    float4 v = reinterpret_cast<const float4*>(E + (size_t)row * EMB)[t];
    float ss = v.x * v.x + v.y * v.y + v.z * v.z + v.w * v.w;
    #pragma unroll
    for (int o = 16; o > 0; o >>= 1)
        ss += __shfl_xor_sync(0xFFFFFFFFu, ss, o);
    __shared__ float ws[4];
    if ((t & 31) == 0) ws[t >> 5] = ss;
    __syncthreads();
    float tot = ws[0] + ws[1] + ws[2] + ws[3];
    float inv = rsqrtf(fmaxf(tot, 1e-12f));
    __half2* eh = reinterpret_cast<__half2*>(Eh + (size_t)row * EMB + t * 4);
    eh[0] = __floats2half2_rn(v.x, v.y);
    eh[1] = __floats2half2_rn(v.z, v.w);
    __half2* nh = reinterpret_cast<__half2*>(Nrmh + (size_t)row * EMB + t * 4);
    nh[0] = __floats2half2_rn(v.x * inv, v.y * inv);
    nh[1] = __floats2half2_rn(v.z * inv, v.w * inv);
}

// f32 -> fp16 convert, contiguous, zero-padded beyond validElems
__global__ void convert_pad_kernel(const float* __restrict__ in,
                                   __half* __restrict__ out,
                                   long validElems, long total8) {
    long i = (long)blockIdx.x * blockDim.x + threadIdx.x;
    if (i >= total8) return;
    long e = i * 8;
    __half2 h[4];
    if (e + 8 <= validElems) {
        float4 a = *reinterpret_cast<const float4*>(in + e);
        float4 b = *reinterpret_cast<const float4*>(in + e + 4);
        h[0] = __floats2half2_rn(a.x, a.y);
        h[1] = __floats2half2_rn(a.z, a.w);
        h[2] = __floats2half2_rn(b.x, b.y);
        h[3] = __floats2half2_rn(b.z, b.w);
    } else {
        h[0] = h[1] = h[2] = h[3] = __floats2half2_rn(0.f, 0.f);
    }
    __half2* dst = reinterpret_cast<__half2*>(out + e);
    dst[0] = h[0]; dst[1] = h[1]; dst[2] = h[2]; dst[3] = h[3];
}

// f32 [K][C] -> fp16 written into out[k][colOff + c] with row stride ldo
__global__ void convert_cols_kernel(const float* __restrict__ in,
                                    __half* __restrict__ out,
                                    int C, int ldo, int colOff, int total8) {
    int i = blockIdx.x * blockDim.x + threadIdx.x;
    if (i >= total8) return;
    long e = (long)i * 8;
    int k = (int)(e / C);
    int c = (int)(e - (long)k * C);
    float4 a = *reinterpret_cast<const float4*>(in + e);
    float4 b = *reinterpret_cast<const float4*>(in + e + 4);
    __half2* dst = reinterpret_cast<__half2*>(out + (size_t)k * ldo + colOff + c);
    dst[0] = __floats2half2_rn(a.x, a.y);
    dst[1] = __floats2half2_rn(a.z, a.w);
    dst[2] = __floats2half2_rn(b.x, b.y);
    dst[3] = __floats2half2_rn(b.z, b.w);
}

__global__ void concat2_kernel(const float* __restrict__ a,
                               const float* __restrict__ b,
                               float* __restrict__ o, int n) {
    int i = blockIdx.x * blockDim.x + threadIdx.x;
    if (i < n) o[i] = a[i];
    else if (i < 2 * n) o[i] = b[i - n];
}

// ---------------------------------------------------------------------------
// fp16 tensor-core GEMM.
//   TRANSB=false: C = act(A[M,K] @ Bt[N,K]^T + bias)   (B K-major)
//   TRANSB=true : C = act(A[M,K] @ B[K,N] + bias)      (B row-major [K][N])
//   ACT_NONE (split-K): raw f32 partial, no bias; blockIdx.z selects the
//   K-slice (A += z*K cols, B += z*K rows) and the output partial buffer.
//   Dual mode: CTAs with blockIdx.y >= nSplit use the second pointer set.
//   CTA tile 128x128, BK=64, 3-stage cp.async (96KB), 2 CTAs/SM, 8 warps.
// ---------------------------------------------------------------------------
enum { ACT_RELU = 0, ACT_SIG = 1, ACT_NEG = 2, ACT_NONE = 3 };
#define BK 64
#define NSTAGE 3
#define ASZ 16384                 // A: 128 rows * 128B ; B(trans): 64 rows * 256B
#define SSZ 32768                 // A + B per stage

template<int ACT, bool HAS_BIAS, bool OUT_HALF, bool TRANSB>
__global__ __launch_bounds__(256, 2)
void hmma_gemm(const __half* __restrict__ Ap, const __half* __restrict__ Bp,
               const float* __restrict__ biasp, void* __restrict__ Coutp,
               int M, int N, int K, int lda, int ldb,
               const __half* A2, const __half* B2,
               const float* bias2, void* Cout2, int nSplit) {
    extern __shared__ __align__(128) char smem[];
    const uint32_t sbase = smem_u32(smem);

    const __half* A   = Ap;
    const __half* Bt  = Bp;
    const float* bias = biasp;
    void* Cout        = Coutp;
    int by = blockIdx.y;
    if (by >= nSplit) {
        by -= nSplit;
        A = A2; Bt = B2; bias = bias2; Cout = Cout2;
    }
    if (ACT == ACT_NONE) {  // split-K slice select
        const int z = blockIdx.z;
        A  += (size_t)z * K;                 // K columns forward
        Bt += (size_t)z * K * ldb;           // K rows forward ([K][N] layout)
        Cout = (float*)Cout + (size_t)z * M * N;
    }

    const int tid = threadIdx.x;
    const int lane = tid & 31, wid = tid >> 5;
    const int wm = (wid & 1) * 64;        // warp m offset in tile
    const int wn = (wid >> 1) * 32;       // warp n offset in tile
    const int m0 = blockIdx.x * 128;
    const int n0 = by * 128;
    const int nch = K / BK;

    float acc[4][4][4];
    #pragma unroll
    for (int i = 0; i < 4; i++)
        #pragma unroll
        for (int j = 0; j < 4; j++)
            #pragma unroll
            for (int q = 0; q < 4; q++) acc[i][j][q] = 0.f;

    // ---- stage loader ----
    auto load_stage = [&](int ch, int st) {
        const int k0 = ch * BK;
        const uint32_t sA = sbase + st * SSZ;
        const uint32_t sB = sA + ASZ;
        #pragma unroll
        for (int u = 0; u < 4; u++) {
            int idx = tid + u * 256;
            int r = idx >> 3, c = idx & 7;
            const __half* src = A + (size_t)(m0 + r) * lda + k0 + c * 8;
            cp16(sA + r * 128 + ((c ^ (r & 7)) << 4), src, 16);
        }
        if constexpr (!TRANSB) {
            #pragma unroll
            for (int u = 0; u < 4; u++) {
                int idx = tid + u * 256;
                int r = idx >> 3, c = idx & 7;
                int n = n0 + r;
                const __half* src = Bt + (size_t)n * ldb + k0 + c * 8;
                cp16(sB + r * 128 + ((c ^ (r & 7)) << 4), src, (n < N) ? 16 : 0);
            }
        } else {
            // B tile [BK=64 k-rows][128 n], 256B per k-row, per-128B-half swizzle
            #pragma unroll
            for (int u = 0; u < 4; u++) {
                int idx = tid + u * 256;
                int k = idx >> 4, c = idx & 15;
                const __half* src = Bt + (size_t)(k0 + k) * ldb + n0 + c * 8;
                uint32_t dst = sB + k * 256 + ((c >> 3) << 7)
                             + (((c & 7) ^ (k & 7)) << 4);
                cp16(dst, src, (n0 + c * 8 + 8 <= N) ? 16 : 0);
            }
        }
        CP_COMMIT();
    };

    // ldmatrix lane addressing
    const int aRow = wm + (lane & 15);
    const int aKsel = lane >> 4;
    const int swz = lane & 7;
    // non-trans B
    const int bRow = wn + ((lane >> 4) << 3) + (lane & 7);
    const int bKsel = (lane >> 3) & 1;
    // trans B: lane -> k row within k16, plus two n-octet byte offsets
    const int kLane = ((lane >> 3) & 1) * 8 + (lane & 7);
    int bOffT0 = 0, bOffT1 = 0;
    {
        int n0l = wn + ((lane >> 4) << 3);
        int c0 = n0l >> 3, c1 = (n0l + 16) >> 3;
        bOffT0 = ((c0 >> 3) << 7) + (((c0 & 7) ^ (lane & 7)) << 4);
        bOffT1 = ((c1 >> 3) << 7) + (((c1 & 7) ^ (lane & 7)) << 4);
    }

    load_stage(0, 0);
    load_stage(1, 1);

    for (int i = 0; i < nch; i++) {
        const int j = i + NSTAGE - 1;
        if (j < nch) load_stage(j, j % NSTAGE);
        else         CP_COMMIT();           // keep wait count aligned
        CP_WAIT(NSTAGE - 1);
        __syncthreads();

        const uint32_t sA = sbase + (i % NSTAGE) * SSZ;
        const uint32_t sB = sA + ASZ;
        #pragma unroll
        for (int kk = 0; kk < 4; kk++) {
            uint32_t a[4][4], b[2][4];
            const uint32_t aByte = ((2 * kk + aKsel) ^ swz) << 4;
            #pragma unroll
            for (int mf = 0; mf < 4; mf++)
                LDSM_X4(a[mf], sA + (aRow + 16 * mf) * 128 + aByte);
            if constexpr (!TRANSB) {
                const uint32_t bByte = ((2 * kk + bKsel) ^ swz) << 4;
                #pragma unroll
                for (int nf2 = 0; nf2 < 2; nf2++)
                    LDSM_X4(b[nf2], sB + (bRow + 16 * nf2) * 128 + bByte);
            } else {
                const uint32_t rowB = sB + (kk * 16 + kLane) * 256;
                LDSM_X4_T(b[0], rowB + bOffT0);
                LDSM_X4_T(b[1], rowB + bOffT1);
            }
            #pragma unroll
            for (int mf = 0; mf < 4; mf++)
                #pragma unroll
                for (int nf = 0; nf < 4; nf++)
                    mma16816(acc[mf][nf], a[mf],
                             b[nf >> 1][(nf & 1) * 2],
                             b[nf >> 1][(nf & 1) * 2 + 1]);
        }
        __syncthreads();
    }

    // ---- epilogue ----
    #pragma unroll
    for (int mf = 0; mf < 4; mf++) {
        const int row = m0 + wm + mf * 16 + (lane >> 2);
        #pragma unroll
        for (int nf = 0; nf < 4; nf++) {
            const int col = n0 + wn + nf * 8 + 2 * (lane & 3);
            if (col >= N) continue;
            float2 lo = make_float2(acc[mf][nf][0], acc[mf][nf][1]);
            float2 hi = make_float2(acc[mf][nf][2], acc[mf][nf][3]);
            if (HAS_BIAS) {
                float2 bb = *reinterpret_cast<const float2*>(bias + col);
                lo.x += bb.x; lo.y += bb.y;
                hi.x += bb.x; hi.y += bb.y;
            }
            if (ACT == ACT_RELU) {
                lo.x = fmaxf(lo.x, 0.f); lo.y = fmaxf(lo.y, 0.f);
                hi.x = fmaxf(hi.x, 0.f); hi.y = fmaxf(hi.y, 0.f);
            } else if (ACT == ACT_SIG) {
                lo.x = 1.f / (1.f + __expf(-lo.x));
                lo.y = 1.f / (1.f + __expf(-lo.y));
                hi.x = 1.f / (1.f + __expf(-hi.x));
                hi.y = 1.f / (1.f + __expf(-hi.y));
            } else if (ACT == ACT_NEG) {
                lo.x = -lo.x; lo.y = -lo.y;
                hi.x = -hi.x; hi.y = -hi.y;
            }  // ACT_NONE: raw
            if (OUT_HALF) {
                __half* C = (__half*)Cout;
                *reinterpret_cast<__half2*>(C + (size_t)row * N + col) =
                    __floats2half2_rn(lo.x, lo.y);
                *reinterpret_cast<__half2*>(C + (size_t)(row + 8) * N + col) =
                    __floats2half2_rn(hi.x, hi.y);
            } else {
                float* C = (float*)Cout;
                *reinterpret_cast<float2*>(C + (size_t)row * N + col) = lo;
                *reinterpret_cast<float2*>(C + (size_t)(row + 8) * N + col) = hi;
            }
        }
    }
}

#define NO_DUAL nullptr, nullptr, nullptr, nullptr, 0x40000000

// ---------------------------------------------------------------------------
// Launch (serial; split-K gemm1 is the 4th launch so ncu profiles it)
// ---------------------------------------------------------------------------
extern "C" void kernel_launch(void* const* d_in, const int* in_sizes, int n_in,
                              void* d_out, int out_size) {
    const float* likes  = (const float*)d_in[1];
    const void*  nmask  = d_in[2];
    const float* enc_w1 = (const float*)d_in[3];
    const float* enc_b1 = (const float*)d_in[4];
    const float* enc_w2 = (const float*)d_in[5];
    const float* enc_b2 = (const float*)d_in[6];
    const float* lk_w1  = (const float*)d_in[7];
    const float* lk_b1  = (const float*)d_in[8];
    const float* lk_w2  = (const float*)d_in[9];
    const float* lk_b2  = (const float*)d_in[10];
    const float* rc_w1  = (const float*)d_in[11];
    const float* rc_b1  = (const float*)d_in[12];
    const float* rc_w2  = (const float*)d_in[13];
    const float* rc_b2  = (const float*)d_in[14];

    float* out       = (float*)d_out;
    float* out_likes = out;
    float* out_sim   = out_likes + (size_t)BATCH * NITEMS;
    float* out_rec   = out_sim + (size_t)BATCH * BATCH;
    float* out_pop   = out_rec + (size_t)BATCH * NITEMS;

    __half *noisyh, *W1c, *W2c, *Wlr, *W4c, *W6c, *Hh, *Hh2, *Eh, *Nrmh;
    float *E, *part, *blr, *psum;
    cudaGetSymbolAddress((void**)&noisyh, g_noisyh);
    cudaGetSymbolAddress((void**)&W1c, g_W1c);
    cudaGetSymbolAddress((void**)&W2c, g_W2c);
    cudaGetSymbolAddress((void**)&Wlr, g_Wlr);
    cudaGetSymbolAddress((void**)&W4c, g_W4c);
    cudaGetSymbolAddress((void**)&W6c, g_W6c);
    cudaGetSymbolAddress((void**)&blr, g_blr);
    cudaGetSymbolAddress((void**)&psum, g_psum);
    cudaGetSymbolAddress((void**)&Hh, g_Hh);
    cudaGetSymbolAddress((void**)&Hh2, g_Hh2);
    cudaGetSymbolAddress((void**)&E, g_E);
    cudaGetSymbolAddress((void**)&Eh, g_Eh);
    cudaGetSymbolAddress((void**)&Nrmh, g_Nrmh);
    cudaGetSymbolAddress((void**)&part, g_part);

    const int smem = NSTAGE * SSZ;  // 96KB
    cudaFuncSetAttribute(hmma_gemm<ACT_NONE, false, false, true>,
                         cudaFuncAttributeMaxDynamicSharedMemorySize, smem);
    cudaFuncSetAttribute(hmma_gemm<ACT_RELU, true, true, true>,
                         cudaFuncAttributeMaxDynamicSharedMemorySize, smem);
    cudaFuncSetAttribute(hmma_gemm<ACT_RELU, true, false, true>,
                         cudaFuncAttributeMaxDynamicSharedMemorySize, smem);
    cudaFuncSetAttribute(hmma_gemm<ACT_SIG, true, false, true>,
                         cudaFuncAttributeMaxDynamicSharedMemorySize, smem);
    cudaFuncSetAttribute(hmma_gemm<ACT_NEG, false, false, false>,
                         cudaFuncAttributeMaxDynamicSharedMemorySize, smem);

    // 1: mask probe
    probe_mask_kernel<<<1, 256>>>((const unsigned int*)nmask);
    // 2: fused denoise + popular partials
    premask_popular_kernel<<<dim3((KPAD + 255) / 256, 16), 256>>>(
        likes, nmask, noisyh, part);
    // 3: convert enc_w1 [20000][1024] -> fp16 [20096][1024] (zero-pad rows)
    {
        long valid = (long)NITEMS * HID;
        long tot8 = (long)KPAD * HID / 8;
        convert_pad_kernel<<<(int)((tot8 + 255) / 256), 256>>>(
            enc_w1, W1c, valid, tot8);
    }
    // 4: big encoder GEMM, split-K x2 (profiled): psum[z] = noisy @ enc_w1
    hmma_gemm<ACT_NONE, false, false, true>
        <<<dim3(BATCH / 128, HID / 128, 2), 256, smem>>>(
        noisyh, W1c, nullptr, psum, BATCH, HID, KHALF, KPAD, HID, NO_DUAL);
    // 5: combine partials -> Hh = fp16(relu(p0+p1+b1))
    combine_splitk_kernel<<<(int)(((size_t)BATCH * HID / 4 + 255) / 256), 256>>>(
        psum, enc_b1, Hh);

    // popular reduce + remaining converts
    popular_reduce_kernel<<<(NITEMS + 255) / 256, 256>>>(part, out_pop);
    {
        long tot8 = (long)HID * EMB / 8;
        convert_pad_kernel<<<(int)((tot8 + 255) / 256), 256>>>(
            enc_w2, W2c, (long)HID * EMB, tot8);
    }
    {
        int tot8 = EMB * HID / 8;
        convert_cols_kernel<<<(tot8 + 255) / 256, 256>>>(
            lk_w1, Wlr, HID, 2 * HID, 0, tot8);
        convert_cols_kernel<<<(tot8 + 255) / 256, 256>>>(
            rc_w1, Wlr, HID, 2 * HID, HID, tot8);
    }
    concat2_kernel<<<(2 * HID + 255) / 256, 256>>>(lk_b1, rc_b1, blr, HID);
    {
        long tot8 = (long)HID * NITEMS / 8;
        convert_pad_kernel<<<(int)((tot8 + 255) / 256), 256>>>(
            lk_w2, W4c, (long)HID * NITEMS, tot8);
        convert_pad_kernel<<<(int)((tot8 + 255) / 256), 256>>>(
            rc_w2, W6c, (long)HID * NITEMS, tot8);
    }

    // encoder layer 2 + norm
    hmma_gemm<ACT_RELU, true, false, true>
        <<<dim3(BATCH / 128, EMB / 128), 256, smem>>>(
        Hh, W2c, enc_b2, E, BATCH, EMB, HID, HID, EMB, NO_DUAL);
    norm_half_kernel<<<BATCH, 128>>>(E, Nrmh, Eh);

    // user_sim = -(Nrm @ Nrm^T)   (K-major B path)
    hmma_gemm<ACT_NEG, false, false, false>
        <<<dim3(BATCH / 128, BATCH / 128), 256, smem>>>(
        Nrmh, Nrmh, nullptr, out_sim, BATCH, BATCH, EMB, EMB, EMB, NO_DUAL);

    // fused head hiddens: Hh2 = relu(Eh @ [lk_w1 | rc_w1] + [b|b])  [2048][2048]
    hmma_gemm<ACT_RELU, true, true, true>
        <<<dim3(BATCH / 128, (2 * HID) / 128), 256, smem>>>(
        Eh, Wlr, blr, Hh2, BATCH, 2 * HID, EMB, EMB, 2 * HID, NO_DUAL);

    // BOTH head outputs in ONE launch (wave merge): y-tiles [0,157) likes,
    // [157,314) rec. 5024 CTAs = 16.97 waves.
    const int nTiles = (NITEMS + 127) / 128;  // 157
    hmma_gemm<ACT_SIG, true, false, true>
        <<<dim3(BATCH / 128, 2 * nTiles), 256, smem>>>(
        Hh2, W4c, lk_b2, out_likes, BATCH, NITEMS, HID, 2 * HID, NITEMS,
        Hh2 + HID, W6c, rc_b2, out_rec, nTiles);
}

// round 11
// speedup vs baseline: 1.2185x; 1.0412x over previous
#include <cuda_runtime.h>
#include <cuda_fp16.h>
#include <cstdint>

// Problem constants
#define BATCH  2048
#define NITEMS 20000
#define KPAD   20096   // NITEMS padded to 2 x 10048 (157 x 64 per K-split)
#define KHALF  10048
#define EMB    512
#define HID    1024    // 2*D

// ---------------------------------------------------------------------------
// Scratch (no allocations -> __device__ globals)
// ---------------------------------------------------------------------------
__device__ __half g_noisyh[(size_t)BATCH * KPAD];    // masked likes fp16, padded
__device__ __half g_W1c[(size_t)KPAD * HID];         // enc_w1 fp16 [20096][1024]
__device__ __half g_W2c[(size_t)HID * EMB];          // enc_w2 fp16 [1024][512]
__device__ __half g_Wlr[(size_t)EMB * (2 * HID)];    // [512][2048] = lk_w1 ++ rc_w1
__device__ __half g_W4c[(size_t)HID * NITEMS];       // lk_w2 fp16 [1024][20000]
__device__ __half g_W6c[(size_t)HID * NITEMS];       // rc_w2 fp16 [1024][20000]
__device__ float  g_blr[2 * HID];                    // lk_b1 ++ rc_b1
__device__ float  g_psum[2 * (size_t)BATCH * HID];   // split-K partials (f32)
__device__ __half g_Hh[(size_t)BATCH * HID];         // encoder hidden fp16
__device__ __half g_Hh2[(size_t)BATCH * 2 * HID];    // fused head hiddens fp16
__device__ float  g_E[(size_t)BATCH * EMB];          // embed f32
__device__ __half g_Eh[(size_t)BATCH * EMB];         // embed fp16
__device__ __half g_Nrmh[(size_t)BATCH * EMB];       // normalized fp16
__device__ float  g_part[16 * NITEMS];
__device__ int    g_mask_mode;  // 0=u8, 1=i32, 2=f32

// ---------------------------------------------------------------------------
// PTX helpers (arch-generic sm_80-era instructions)
// ---------------------------------------------------------------------------
__device__ __forceinline__ uint32_t smem_u32(const void* p) {
    uint32_t a;
    asm("{ .reg .u64 t; cvta.to.shared.u64 t, %1; cvt.u32.u64 %0, t; }"
        : "=r"(a) : "l"(p));
    return a;
}
__device__ __forceinline__ void cp16(uint32_t dst, const void* src, int sz) {
    asm volatile("cp.async.cg.shared.global [%0], [%1], 16, %2;"
        :: "r"(dst), "l"(src), "r"(sz));
}
#define CP_COMMIT() asm volatile("cp.async.commit_group;" ::: "memory")
#define CP_WAIT(n)  asm volatile("cp.async.wait_group %0;" :: "n"(n) : "memory")

#define LDSM_X4(r, addr) \
    asm volatile("ldmatrix.sync.aligned.m8n8.x4.shared.b16 {%0,%1,%2,%3}, [%4];" \
        : "=r"((r)[0]), "=r"((r)[1]), "=r"((r)[2]), "=r"((r)[3]) : "r"(addr))

#define LDSM_X4_T(r, addr) \
    asm volatile("ldmatrix.sync.aligned.m8n8.x4.trans.shared.b16 {%0,%1,%2,%3}, [%4];" \
        : "=r"((r)[0]), "=r"((r)[1]), "=r"((r)[2]), "=r"((r)[3]) : "r"(addr))

__device__ __forceinline__ void mma16816(float* d, const uint32_t* a,
                                         uint32_t b0, uint32_t b1) {
    asm volatile(
        "mma.sync.aligned.m16n8k16.row.col.f32.f16.f16.f32 "
        "{%0,%1,%2,%3}, {%4,%5,%6,%7}, {%8,%9}, {%0,%1,%2,%3};"
        : "+f"(d[0]), "+f"(d[1]), "+f"(d[2]), "+f"(d[3])
        : "r"(a[0]), "r"(a[1]), "r"(a[2]), "r"(a[3]), "r"(b0), "r"(b1));
}

enum { ACT_RELU = 0, ACT_SIG = 1, ACT_NEG = 2, ACT_NONE = 3 };
#define BK 64
#define NSTAGE 3
#define ASZ 16384                 // A: 128 rows * 128B ; B(trans): 64 rows * 256B
#define SSZ 32768                 // A + B per stage

// ---------------------------------------------------------------------------
// GEMM body (device fn; shared by standalone kernel and the MEGA kernel).
//   TRANSB=false: C = act(A[M,K] @ Bt[N,K]^T + bias)   (B K-major)
//   TRANSB=true : C = act(A[M,K] @ B[K,N] + bias)      (B row-major [K][N])
// ---------------------------------------------------------------------------
template<int ACT, bool HAS_BIAS, bool OUT_HALF, bool TRANSB>
__device__ __forceinline__ void gemm_body(
    const __half* __restrict__ A, const __half* __restrict__ Bt,
    const float* __restrict__ bias, void* __restrict__ Cout,
    int M, int N, int K, int lda, int ldb, int bx, int by, char* smem) {
    const uint32_t sbase = smem_u32(smem);

    const int tid = threadIdx.x;
    const int lane = tid & 31, wid = tid >> 5;
    const int wm = (wid & 1) * 64;        // warp m offset in tile
    const int wn = (wid >> 1) * 32;       // warp n offset in tile
    const int m0 = bx * 128;
    const int n0 = by * 128;
    const int nch = K / BK;

    float acc[4][4][4];
    #pragma unroll
    for (int i = 0; i < 4; i++)
        #pragma unroll
        for (int j = 0; j < 4; j++)
            #pragma unroll
            for (int q = 0; q < 4; q++) acc[i][j][q] = 0.f;

    // ---- stage loader ----
    auto load_stage = [&](int ch, int st) {
        const int k0 = ch * BK;
        const uint32_t sA = sbase + st * SSZ;
        const uint32_t sB = sA + ASZ;
        #pragma unroll
        for (int u = 0; u < 4; u++) {
            int idx = tid + u * 256;
            int r = idx >> 3, c = idx & 7;
            const __half* src = A + (size_t)(m0 + r) * lda + k0 + c * 8;
            cp16(sA + r * 128 + ((c ^ (r & 7)) << 4), src, 16);
        }
        if constexpr (!TRANSB) {
            #pragma unroll
            for (int u = 0; u < 4; u++) {
                int idx = tid + u * 256;
                int r = idx >> 3, c = idx & 7;
                int n = n0 + r;
                const __half* src = Bt + (size_t)n * ldb + k0 + c * 8;
                cp16(sB + r * 128 + ((c ^ (r & 7)) << 4), src, (n < N) ? 16 : 0);
            }
        } else {
            // B tile [BK=64 k-rows][128 n], 256B per k-row, per-128B-half swizzle
            #pragma unroll
            for (int u = 0; u < 4; u++) {
                int idx = tid + u * 256;
                int k = idx >> 4, c = idx & 15;
                const __half* src = Bt + (size_t)(k0 + k) * ldb + n0 + c * 8;
                uint32_t dst = sB + k * 256 + ((c >> 3) << 7)
                             + (((c & 7) ^ (k & 7)) << 4);
                cp16(dst, src, (n0 + c * 8 + 8 <= N) ? 16 : 0);
            }
        }
        CP_COMMIT();
    };

    // ldmatrix lane addressing
    const int aRow = wm + (lane & 15);
    const int aKsel = lane >> 4;
    const int swz = lane & 7;
    // non-trans B
    const int bRow = wn + ((lane >> 4) << 3) + (lane & 7);
    const int bKsel = (lane >> 3) & 1;
    // trans B: lane -> k row within k16, plus two n-octet byte offsets
    const int kLane = ((lane >> 3) & 1) * 8 + (lane & 7);
    int bOffT0 = 0, bOffT1 = 0;
    {
        int n0l = wn + ((lane >> 4) << 3);
        int c0 = n0l >> 3, c1 = (n0l + 16) >> 3;
        bOffT0 = ((c0 >> 3) << 7) + (((c0 & 7) ^ (lane & 7)) << 4);
        bOffT1 = ((c1 >> 3) << 7) + (((c1 & 7) ^ (lane & 7)) << 4);
    }

    load_stage(0, 0);
    load_stage(1, 1);

    for (int i = 0; i < nch; i++) {
        const int j = i + NSTAGE - 1;
        if (j < nch) load_stage(j, j % NSTAGE);
        else         CP_COMMIT();           // keep wait count aligned
        CP_WAIT(NSTAGE - 1);
        __syncthreads();

        const uint32_t sA = sbase + (i % NSTAGE) * SSZ;
        const uint32_t sB = sA + ASZ;
        #pragma unroll
        for (int kk = 0; kk < 4; kk++) {
            uint32_t a[4][4], b[2][4];
            const uint32_t aByte = ((2 * kk + aKsel) ^ swz) << 4;
            #pragma unroll
            for (int mf = 0; mf < 4; mf++)
                LDSM_X4(a[mf], sA + (aRow + 16 * mf) * 128 + aByte);
            if constexpr (!TRANSB) {
                const uint32_t bByte = ((2 * kk + bKsel) ^ swz) << 4;
                #pragma unroll
                for (int nf2 = 0; nf2 < 2; nf2++)
                    LDSM_X4(b[nf2], sB + (bRow + 16 * nf2) * 128 + bByte);
            } else {
                const uint32_t rowB = sB + (kk * 16 + kLane) * 256;
                LDSM_X4_T(b[0], rowB + bOffT0);
                LDSM_X4_T(b[1], rowB + bOffT1);
            }
            #pragma unroll
            for (int mf = 0; mf < 4; mf++)
                #pragma unroll
                for (int nf = 0; nf < 4; nf++)
                    mma16816(acc[mf][nf], a[mf],
                             b[nf >> 1][(nf & 1) * 2],
                             b[nf >> 1][(nf & 1) * 2 + 1]);
        }
        __syncthreads();
    }

    // ---- epilogue ----
    #pragma unroll
    for (int mf = 0; mf < 4; mf++) {
        const int row = m0 + wm + mf * 16 + (lane >> 2);
        #pragma unroll
        for (int nf = 0; nf < 4; nf++) {
            const int col = n0 + wn + nf * 8 + 2 * (lane & 3);
            if (col >= N) continue;
            float2 lo = make_float2(acc[mf][nf][0], acc[mf][nf][1]);
            float2 hi = make_float2(acc[mf][nf][2], acc[mf][nf][3]);
            if (HAS_BIAS) {
                float2 bb = *reinterpret_cast<const float2*>(bias + col);
                lo.x += bb.x; lo.y += bb.y;
                hi.x += bb.x; hi.y += bb.y;
            }
            if (ACT == ACT_RELU) {
                lo.x = fmaxf(lo.x, 0.f); lo.y = fmaxf(lo.y, 0.f);
                hi.x = fmaxf(hi.x, 0.f); hi.y = fmaxf(hi.y, 0.f);
            } else if (ACT == ACT_SIG) {
                lo.x = 1.f / (1.f + __expf(-lo.x));
                lo.y = 1.f / (1.f + __expf(-lo.y));
                hi.x = 1.f / (1.f + __expf(-hi.x));
                hi.y = 1.f / (1.f + __expf(-hi.y));
            } else if (ACT == ACT_NEG) {
                lo.x = -lo.x; lo.y = -lo.y;
                hi.x = -hi.x; hi.y = -hi.y;
            }  // ACT_NONE: raw
            if (OUT_HALF) {
                __half* C = (__half*)Cout;
                *reinterpret_cast<__half2*>(C + (size_t)row * N + col) =
                    __floats2half2_rn(lo.x, lo.y);
                *reinterpret_cast<__half2*>(C + (size_t)(row + 8) * N + col) =
                    __floats2half2_rn(hi.x, hi.y);
            } else {
                float* C = (float*)Cout;
                *reinterpret_cast<float2*>(C + (size_t)row * N + col) = lo;
                *reinterpret_cast<float2*>(C + (size_t)(row + 8) * N + col) = hi;
            }
        }
    }
}

// ---------------------------------------------------------------------------
// Standalone GEMM kernel (with dual-pointer wave-merge mode)
// ---------------------------------------------------------------------------
template<int ACT, bool HAS_BIAS, bool OUT_HALF, bool TRANSB>
__global__ __launch_bounds__(256, 2)
void hmma_gemm(const __half* __restrict__ Ap, const __half* __restrict__ Bp,
               const float* __restrict__ biasp, void* __restrict__ Coutp,
               int M, int N, int K, int lda, int ldb,
               const __half* A2, const __half* B2,
               const float* bias2, void* Cout2, int nSplit) {
    extern __shared__ __align__(128) char smem[];
    const __half* A   = Ap;
    const __half* Bt  = Bp;
    const float* bias = biasp;
    void* Cout        = Coutp;
    int by = blockIdx.y;
    if (by >= nSplit) {
        by -= nSplit;
        A = A2; Bt = B2; bias = bias2; Cout = Cout2;
    }
    gemm_body<ACT, HAS_BIAS, OUT_HALF, TRANSB>(
        A, Bt, bias, Cout, M, N, K, lda, ldb, blockIdx.x, by, smem);
}

// ---------------------------------------------------------------------------
// Aux device helpers (block-indexed bodies of the prep kernels)
// ---------------------------------------------------------------------------
__device__ __forceinline__ void aux_popular_reduce(
    int b, const float* __restrict__ part, float* __restrict__ out_pop) {
    int i = b * 256 + threadIdx.x;
    if (i >= NITEMS) return;
    float s = 0.f;
    #pragma unroll
    for (int c = 0; c < 16; c++) s += part[c * NITEMS + i];
    out_pop[i] = s * (1.0f / (float)BATCH);
}

__device__ __forceinline__ void aux_convert_pad(
    int b, const float* __restrict__ in, __half* __restrict__ out,
    long validElems, long total8) {
    long i = (long)b * 256 + threadIdx.x;
    if (i >= total8) return;
    long e = i * 8;
    __half2 h[4];
    if (e + 8 <= validElems) {
        float4 a = *reinterpret_cast<const float4*>(in + e);
        float4 bb = *reinterpret_cast<const float4*>(in + e + 4);
        h[0] = __floats2half2_rn(a.x, a.y);
        h[1] = __floats2half2_rn(a.z, a.w);
        h[2] = __floats2half2_rn(bb.x, bb.y);
        h[3] = __floats2half2_rn(bb.z, bb.w);
    } else {
        h[0] = h[1] = h[2] = h[3] = __floats2half2_rn(0.f, 0.f);
    }
    __half2* dst = reinterpret_cast<__half2*>(out + e);
    dst[0] = h[0]; dst[1] = h[1]; dst[2] = h[2]; dst[3] = h[3];
}

__device__ __forceinline__ void aux_convert_cols(
    int b, const float* __restrict__ in, __half* __restrict__ out,
    int C, int ldo, int colOff, int total8) {
    int i = b * 256 + threadIdx.x;
    if (i >= total8) return;
    long e = (long)i * 8;
    int k = (int)(e / C);
    int c = (int)(e - (long)k * C);
    float4 a = *reinterpret_cast<const float4*>(in + e);
    float4 bb = *reinterpret_cast<const float4*>(in + e + 4);
    __half2* dst = reinterpret_cast<__half2*>(out + (size_t)k * ldo + colOff + c);
    dst[0] = __floats2half2_rn(a.x, a.y);
    dst[1] = __floats2half2_rn(a.z, a.w);
    dst[2] = __floats2half2_rn(bb.x, bb.y);
    dst[3] = __floats2half2_rn(bb.z, bb.w);
}

__device__ __forceinline__ void aux_concat2(
    int b, const float* __restrict__ a, const float* __restrict__ bsrc,
    float* __restrict__ o, int n) {
    int i = b * 256 + threadIdx.x;
    if (i < n) o[i] = a[i];
    else if (i < 2 * n) o[i] = bsrc[i - n];
}

// ---------------------------------------------------------------------------
// MEGA kernel: split-K gemm1 (bids 0..255) + ALL independent prep work
// (popular_reduce, W2/Wlr/blr/W4/W6 converts) as extra short CTAs.
// First wave = 256 gemm + 40 aux CTAs = 296 = exactly 2/SM; aux CTAs stream
// through freed slots while gemm CTAs grind (~240us). Everything completes
// before the next stream-ordered kernel.
// ---------------------------------------------------------------------------
#define MEGA_GEMM 256
#define AUX_RED   79
#define AUX_W2    256
#define AUX_WLR1  256
#define AUX_WLR2  256
#define AUX_BLR   8
#define AUX_W4    10000
#define AUX_W6    10000
#define MEGA_BLOCKS (MEGA_GEMM + AUX_RED + AUX_W2 + AUX_WLR1 + AUX_WLR2 + \
                     AUX_BLR + AUX_W4 + AUX_W6)

__global__ __launch_bounds__(256, 2)
void mega_kernel(const __half* __restrict__ noisyh,
                 const __half* __restrict__ W1c, float* __restrict__ psum,
                 const float* __restrict__ part, float* __restrict__ out_pop,
                 const float* __restrict__ enc_w2, __half* __restrict__ W2c,
                 const float* __restrict__ lk_w1, const float* __restrict__ rc_w1,
                 __half* __restrict__ Wlr,
                 const float* __restrict__ lk_b1, const float* __restrict__ rc_b1,
                 float* __restrict__ blr,
                 const float* __restrict__ lk_w2, __half* __restrict__ W4c,
                 const float* __restrict__ rc_w2, __half* __restrict__ W6c) {
    extern __shared__ __align__(128) char smem[];
    int bid = blockIdx.x;
    if (bid < MEGA_GEMM) {
        int z = bid >> 7;            // K split 0/1
        int bx = bid & 15;           // m tile
        int by = (bid >> 4) & 7;     // n tile
        const __half* A = noisyh + (size_t)z * KHALF;
        const __half* B = W1c + (size_t)z * KHALF * HID;
        float* C = psum + (size_t)z * BATCH * HID;
        gemm_body<ACT_NONE, false, false, true>(
            A, B, nullptr, C, BATCH, HID, KHALF, KPAD, HID, bx, by, smem);
        return;
    }
    int aux = bid - MEGA_GEMM;
    if (aux < AUX_RED) { aux_popular_reduce(aux, part, out_pop); return; }
    aux -= AUX_RED;
    if (aux < AUX_W2) {
        aux_convert_pad(aux, enc_w2, W2c, (long)HID * EMB, (long)HID * EMB / 8);
        return;
    }
    aux -= AUX_W2;
    if (aux < AUX_WLR1) {
        aux_convert_cols(aux, lk_w1, Wlr, HID, 2 * HID, 0, EMB * HID / 8);
        return;
    }
    aux -= AUX_WLR1;
    if (aux < AUX_WLR2) {
        aux_convert_cols(aux, rc_w1, Wlr, HID, 2 * HID, HID, EMB * HID / 8);
        return;
    }
    aux -= AUX_WLR2;
    if (aux < AUX_BLR) { aux_concat2(aux, lk_b1, rc_b1, blr, HID); return; }
    aux -= AUX_BLR;
    if (aux < AUX_W4) {
        aux_convert_pad(aux, lk_w2, W4c, (long)HID * NITEMS,
                        (long)HID * NITEMS / 8);
        return;
    }
    aux -= AUX_W4;
    aux_convert_pad(aux, rc_w2, W6c, (long)HID * NITEMS,
                    (long)HID * NITEMS / 8);
}

// ---------------------------------------------------------------------------
// Small kernels
// ---------------------------------------------------------------------------
__global__ void probe_mask_kernel(const unsigned int* __restrict__ w) {
    __shared__ int s_other, s_f1, s_i1;
    if (threadIdx.x == 0) { s_other = 0; s_f1 = 0; s_i1 = 0; }
    __syncthreads();
    int lo = 0, lf = 0, li = 0;
    for (int i = threadIdx.x; i < 65536; i += blockDim.x) {
        unsigned v = w[i];
        if (v == 0u) continue;
        else if (v == 1u) li++;
        else if (v == 0x3F800000u) lf++;
        else lo++;
    }
    atomicAdd(&s_other, lo); atomicAdd(&s_f1, lf); atomicAdd(&s_i1, li);
    __syncthreads();
    if (threadIdx.x == 0) {
        int mode;
        if (s_other > 1024) mode = 0;
        else if (s_f1 >= s_i1) mode = 2;
        else mode = 1;
        g_mask_mode = mode;
    }
}

// Fused: noisy = where(mask,0,likes) -> fp16 padded AND column partial sums
__global__ void premask_popular_kernel(const float* __restrict__ likes,
                                       const void* __restrict__ mask,
                                       __half* __restrict__ noisy,
                                       float* __restrict__ part) {
    const int mode = g_mask_mode;
    const int col = blockIdx.x * 256 + threadIdx.x;
    if (col >= KPAD) return;
    const int r0 = blockIdx.y * 128;

    if (col >= NITEMS) {  // padding region: zero noisy, no popular
        const __half hz = __float2half_rn(0.f);
        for (int r = 0; r < 128; r++)
            noisy[(size_t)(r0 + r) * KPAD + col] = hz;
        return;
    }

    const unsigned char* m8 = (const unsigned char*)mask;
    const int*           mi = (const int*)mask;
    const float*         mf = (const float*)mask;

    float sum = 0.f;
    #pragma unroll 4
    for (int r = 0; r < 128; r++) {
        size_t e = (size_t)(r0 + r) * NITEMS + col;
        float v = likes[e];
        sum += v;
        bool drop;
        if (mode == 0)      drop = (m8[e] != 0);
        else if (mode == 1) drop = (mi[e] != 0);
        else                drop = (mf[e] != 0.f);
        noisy[(size_t)(r0 + r) * KPAD + col] = __float2half_rn(drop ? 0.f : v);
    }
    part[blockIdx.y * NITEMS + col] = sum;
}

// combine split-K partials: Hh = fp16(relu(p0 + p1 + bias))
__global__ void combine_splitk_kernel(const float* __restrict__ p,
                                      const float* __restrict__ bias,
                                      __half* __restrict__ out) {
    const size_t MN = (size_t)BATCH * HID;
    size_t e = ((size_t)blockIdx.x * 256 + threadIdx.x) * 4;
    if (e >= MN) return;
    int col = (int)(e & (HID - 1));
    float4 a = *reinterpret_cast<const float4*>(p + e);
    float4 b = *reinterpret_cast<const float4*>(p + MN + e);
    float4 bb = *reinterpret_cast<const float4*>(bias + col);
    float x0 = fmaxf(a.x + b.x + bb.x, 0.f);
    float x1 = fmaxf(a.y + b.y + bb.y, 0.f);
    float x2 = fmaxf(a.z + b.z + bb.z, 0.f);
    float x3 = fmaxf(a.w + b.w + bb.w, 0.f);
    __half2* dst = reinterpret_cast<__half2*>(out + e);
    dst[0] = __floats2half2_rn(x0, x1);
    dst[1] = __floats2half2_rn(x2, x3);
}

// per-row l2 normalize; emit fp16 normalized AND fp16 copy of E
__global__ void norm_half_kernel(const float* __restrict__ E,
                                 __half* __restrict__ Nrmh,
                                 __half* __restrict__ Eh) {
    int row = blockIdx.x;
    int t = threadIdx.x;
    float4 v = reinterpret_cast<const float4*>(E + (size_t)row * EMB)[t];
    float ss = v.x * v.x + v.y * v.y + v.z * v.z + v.w * v.w;
    #pragma unroll
    for (int o = 16; o > 0; o >>= 1)
        ss += __shfl_xor_sync(0xFFFFFFFFu, ss, o);
    __shared__ float ws[4];
    if ((t & 31) == 0) ws[t >> 5] = ss;
    __syncthreads();
    float tot = ws[0] + ws[1] + ws[2] + ws[3];
    float inv = rsqrtf(fmaxf(tot, 1e-12f));
    __half2* eh = reinterpret_cast<__half2*>(Eh + (size_t)row * EMB + t * 4);
    eh[0] = __floats2half2_rn(v.x, v.y);
    eh[1] = __floats2half2_rn(v.z, v.w);
    __half2* nh = reinterpret_cast<__half2*>(Nrmh + (size_t)row * EMB + t * 4);
    nh[0] = __floats2half2_rn(v.x * inv, v.y * inv);
    nh[1] = __floats2half2_rn(v.z * inv, v.w * inv);
}

// f32 -> fp16 convert, contiguous, zero-padded beyond validElems (W1c only)
__global__ void convert_pad_kernel(const float* __restrict__ in,
                                   __half* __restrict__ out,
                                   long validElems, long total8) {
    long i = (long)blockIdx.x * blockDim.x + threadIdx.x;
    if (i >= total8) return;
    aux_convert_pad((int)blockIdx.x, in, out, validElems, total8);
}

#define NO_DUAL nullptr, nullptr, nullptr, nullptr, 0x40000000

// ---------------------------------------------------------------------------
// Launch (serial; MEGA is the 4th launch so ncu profiles it)
// ---------------------------------------------------------------------------
extern "C" void kernel_launch(void* const* d_in, const int* in_sizes, int n_in,
                              void* d_out, int out_size) {
    const float* likes  = (const float*)d_in[1];
    const void*  nmask  = d_in[2];
    const float* enc_w1 = (const float*)d_in[3];
    const float* enc_b1 = (const float*)d_in[4];
    const float* enc_w2 = (const float*)d_in[5];
    const float* enc_b2 = (const float*)d_in[6];
    const float* lk_w1  = (const float*)d_in[7];
    const float* lk_b1  = (const float*)d_in[8];
    const float* lk_w2  = (const float*)d_in[9];
    const float* lk_b2  = (const float*)d_in[10];
    const float* rc_w1  = (const float*)d_in[11];
    const float* rc_b1  = (const float*)d_in[12];
    const float* rc_w2  = (const float*)d_in[13];
    const float* rc_b2  = (const float*)d_in[14];

    float* out       = (float*)d_out;
    float* out_likes = out;
    float* out_sim   = out_likes + (size_t)BATCH * NITEMS;
    float* out_rec   = out_sim + (size_t)BATCH * BATCH;
    float* out_pop   = out_rec + (size_t)BATCH * NITEMS;

    __half *noisyh, *W1c, *W2c, *Wlr, *W4c, *W6c, *Hh, *Hh2, *Eh, *Nrmh;
    float *E, *part, *blr, *psum;
    cudaGetSymbolAddress((void**)&noisyh, g_noisyh);
    cudaGetSymbolAddress((void**)&W1c, g_W1c);
    cudaGetSymbolAddress((void**)&W2c, g_W2c);
    cudaGetSymbolAddress((void**)&Wlr, g_Wlr);
    cudaGetSymbolAddress((void**)&W4c, g_W4c);
    cudaGetSymbolAddress((void**)&W6c, g_W6c);
    cudaGetSymbolAddress((void**)&blr, g_blr);
    cudaGetSymbolAddress((void**)&psum, g_psum);
    cudaGetSymbolAddress((void**)&Hh, g_Hh);
    cudaGetSymbolAddress((void**)&Hh2, g_Hh2);
    cudaGetSymbolAddress((void**)&E, g_E);
    cudaGetSymbolAddress((void**)&Eh, g_Eh);
    cudaGetSymbolAddress((void**)&Nrmh, g_Nrmh);
    cudaGetSymbolAddress((void**)&part, g_part);

    const int smem = NSTAGE * SSZ;  // 96KB
    cudaFuncSetAttribute(mega_kernel,
                         cudaFuncAttributeMaxDynamicSharedMemorySize, smem);
    cudaFuncSetAttribute(hmma_gemm<ACT_RELU, true, false, true>,
                         cudaFuncAttributeMaxDynamicSharedMemorySize, smem);
    cudaFuncSetAttribute(hmma_gemm<ACT_RELU, true, true, true>,
                         cudaFuncAttributeMaxDynamicSharedMemorySize, smem);
    cudaFuncSetAttribute(hmma_gemm<ACT_SIG, true, false, true>,
                         cudaFuncAttributeMaxDynamicSharedMemorySize, smem);
    cudaFuncSetAttribute(hmma_gemm<ACT_NEG, false, false, false>,
                         cudaFuncAttributeMaxDynamicSharedMemorySize, smem);

    // 1: mask probe
    probe_mask_kernel<<<1, 256>>>((const unsigned int*)nmask);
    // 2: fused denoise + popular partials
    premask_popular_kernel<<<dim3((KPAD + 255) / 256, 16), 256>>>(
        likes, nmask, noisyh, part);
    // 3: convert enc_w1 -> fp16 [20096][1024] (zero-pad rows); gemm1 needs it
    {
        long valid = (long)NITEMS * HID;
        long tot8 = (long)KPAD * HID / 8;
        convert_pad_kernel<<<(int)((tot8 + 255) / 256), 256>>>(
            enc_w1, W1c, valid, tot8);
    }
    // 4: MEGA -- split-K gemm1 + all independent prep work (profiled)
    mega_kernel<<<MEGA_BLOCKS, 256, smem>>>(
        noisyh, W1c, psum, part, out_pop,
        enc_w2, W2c, lk_w1, rc_w1, Wlr, lk_b1, rc_b1, blr,
        lk_w2, W4c, rc_w2, W6c);
    // 5: combine partials -> Hh = fp16(relu(p0+p1+b1))
    combine_splitk_kernel<<<(int)(((size_t)BATCH * HID / 4 + 255) / 256), 256>>>(
        psum, enc_b1, Hh);

    // encoder layer 2 + norm
    hmma_gemm<ACT_RELU, true, false, true>
        <<<dim3(BATCH / 128, EMB / 128), 256, smem>>>(
        Hh, W2c, enc_b2, E, BATCH, EMB, HID, HID, EMB, NO_DUAL);
    norm_half_kernel<<<BATCH, 128>>>(E, Nrmh, Eh);

    // user_sim = -(Nrm @ Nrm^T)   (K-major B path)
    hmma_gemm<ACT_NEG, false, false, false>
        <<<dim3(BATCH / 128, BATCH / 128), 256, smem>>>(
        Nrmh, Nrmh, nullptr, out_sim, BATCH, BATCH, EMB, EMB, EMB, NO_DUAL);

    // fused head hiddens: Hh2 = relu(Eh @ [lk_w1 | rc_w1] + [b|b])  [2048][2048]
    hmma_gemm<ACT_RELU, true, true, true>
        <<<dim3(BATCH / 128, (2 * HID) / 128), 256, smem>>>(
        Eh, Wlr, blr, Hh2, BATCH, 2 * HID, EMB, EMB, 2 * HID, NO_DUAL);

    // BOTH head outputs in ONE launch (wave merge): y-tiles [0,157) likes,
    // [157,314) rec. 5024 CTAs = 16.97 waves.
    const int nTiles = (NITEMS + 127) / 128;  // 157
    hmma_gemm<ACT_SIG, true, false, true>
        <<<dim3(BATCH / 128, 2 * nTiles), 256, smem>>>(
        Hh2, W4c, lk_b2, out_likes, BATCH, NITEMS, HID, 2 * HID, NITEMS,
        Hh2 + HID, W6c, rc_b2, out_rec, nTiles);
}

// round 12
// speedup vs baseline: 1.2337x; 1.0124x over previous
#include <cuda_runtime.h>
#include <cuda_fp16.h>
#include <cstdint>

// Problem constants
#define BATCH  2048
#define NITEMS 20000
#define KPAD   20096   // NITEMS padded to 2 x 10048 (157 x 64 per K-split)
#define KHALF  10048
#define EMB    512
#define HID    1024    // 2*D

// ---------------------------------------------------------------------------
// Scratch (no allocations -> __device__ globals)
// ---------------------------------------------------------------------------
__device__ __half g_noisyh[(size_t)BATCH * KPAD];    // masked likes fp16, padded
__device__ __half g_W1c[(size_t)KPAD * HID];         // enc_w1 fp16 [20096][1024]
__device__ __half g_W2c[(size_t)HID * EMB];          // enc_w2 fp16 [1024][512]
__device__ __half g_Wlr[(size_t)EMB * (2 * HID)];    // [512][2048] = lk_w1 ++ rc_w1
__device__ __half g_W4c[(size_t)HID * NITEMS];       // lk_w2 fp16 [1024][20000]
__device__ __half g_W6c[(size_t)HID * NITEMS];       // rc_w2 fp16 [1024][20000]
__device__ float  g_blr[2 * HID];                    // lk_b1 ++ rc_b1
__device__ float  g_psum[2 * (size_t)BATCH * HID];   // split-K partials (f32)
__device__ __half g_Hh[(size_t)BATCH * HID];         // encoder hidden fp16
__device__ __half g_Hh2[(size_t)BATCH * 2 * HID];    // fused head hiddens fp16
__device__ float  g_E[(size_t)BATCH * EMB];          // embed f32
__device__ __half g_Eh[(size_t)BATCH * EMB];         // embed fp16
__device__ __half g_Nrmh[(size_t)BATCH * EMB];       // normalized fp16
__device__ float  g_part[16 * NITEMS];
__device__ int    g_mask_mode;  // 0=u8, 1=i32, 2=f32

// ---------------------------------------------------------------------------
// PTX helpers (arch-generic sm_80-era instructions)
// ---------------------------------------------------------------------------
__device__ __forceinline__ uint32_t smem_u32(const void* p) {
    uint32_t a;
    asm("{ .reg .u64 t; cvta.to.shared.u64 t, %1; cvt.u32.u64 %0, t; }"
        : "=r"(a) : "l"(p));
    return a;
}
__device__ __forceinline__ void cp16(uint32_t dst, const void* src, int sz) {
    asm volatile("cp.async.cg.shared.global [%0], [%1], 16, %2;"
        :: "r"(dst), "l"(src), "r"(sz));
}
#define CP_COMMIT() asm volatile("cp.async.commit_group;" ::: "memory")
#define CP_WAIT(n)  asm volatile("cp.async.wait_group %0;" :: "n"(n) : "memory")

#define LDSM_X4(r, addr) \
    asm volatile("ldmatrix.sync.aligned.m8n8.x4.shared.b16 {%0,%1,%2,%3}, [%4];" \
        : "=r"((r)[0]), "=r"((r)[1]), "=r"((r)[2]), "=r"((r)[3]) : "r"(addr))

#define LDSM_X4_T(r, addr) \
    asm volatile("ldmatrix.sync.aligned.m8n8.x4.trans.shared.b16 {%0,%1,%2,%3}, [%4];" \
        : "=r"((r)[0]), "=r"((r)[1]), "=r"((r)[2]), "=r"((r)[3]) : "r"(addr))

__device__ __forceinline__ void mma16816(float* d, const uint32_t* a,
                                         uint32_t b0, uint32_t b1) {
    asm volatile(
        "mma.sync.aligned.m16n8k16.row.col.f32.f16.f16.f32 "
        "{%0,%1,%2,%3}, {%4,%5,%6,%7}, {%8,%9}, {%0,%1,%2,%3};"
        : "+f"(d[0]), "+f"(d[1]), "+f"(d[2]), "+f"(d[3])
        : "r"(a[0]), "r"(a[1]), "r"(a[2]), "r"(a[3]), "r"(b0), "r"(b1));
}

enum { ACT_RELU = 0, ACT_SIG = 1, ACT_NEG = 2, ACT_NONE = 3 };
#define BK 64
#define NSTAGE 3
#define ASZ 16384                 // A: 128 rows * 128B ; B(trans): 64 rows * 256B
#define SSZ 32768                 // A + B per stage

// ---------------------------------------------------------------------------
// GEMM body. Single __syncthreads per K-chunk: 3 smem stages but prefetch
// distance 2, so the stage written at iteration i ((i+2)%3) was last read at
// iteration i-1, which all warps completed before this iteration's barrier.
// cp.async: in-flight groups <= 2; wait_group(1) makes stage i resident.
// ---------------------------------------------------------------------------
template<int ACT, bool HAS_BIAS, bool OUT_HALF, bool TRANSB>
__device__ __forceinline__ void gemm_body(
    const __half* __restrict__ A, const __half* __restrict__ Bt,
    const float* __restrict__ bias, void* __restrict__ Cout,
    int M, int N, int K, int lda, int ldb, int bx, int by, char* smem) {
    const uint32_t sbase = smem_u32(smem);

    const int tid = threadIdx.x;
    const int lane = tid & 31, wid = tid >> 5;
    const int wm = (wid & 1) * 64;        // warp m offset in tile
    const int wn = (wid >> 1) * 32;       // warp n offset in tile
    const int m0 = bx * 128;
    const int n0 = by * 128;
    const int nch = K / BK;

    float acc[4][4][4];
    #pragma unroll
    for (int i = 0; i < 4; i++)
        #pragma unroll
        for (int j = 0; j < 4; j++)
            #pragma unroll
            for (int q = 0; q < 4; q++) acc[i][j][q] = 0.f;

    // ---- stage loader ----
    auto load_stage = [&](int ch, int st) {
        const int k0 = ch * BK;
        const uint32_t sA = sbase + st * SSZ;
        const uint32_t sB = sA + ASZ;
        #pragma unroll
        for (int u = 0; u < 4; u++) {
            int idx = tid + u * 256;
            int r = idx >> 3, c = idx & 7;
            const __half* src = A + (size_t)(m0 + r) * lda + k0 + c * 8;
            cp16(sA + r * 128 + ((c ^ (r & 7)) << 4), src, 16);
        }
        if constexpr (!TRANSB) {
            #pragma unroll
            for (int u = 0; u < 4; u++) {
                int idx = tid + u * 256;
                int r = idx >> 3, c = idx & 7;
                int n = n0 + r;
                const __half* src = Bt + (size_t)n * ldb + k0 + c * 8;
                cp16(sB + r * 128 + ((c ^ (r & 7)) << 4), src, (n < N) ? 16 : 0);
            }
        } else {
            // B tile [BK=64 k-rows][128 n], 256B per k-row, per-128B-half swizzle
            #pragma unroll
            for (int u = 0; u < 4; u++) {
                int idx = tid + u * 256;
                int k = idx >> 4, c = idx & 15;
                const __half* src = Bt + (size_t)(k0 + k) * ldb + n0 + c * 8;
                uint32_t dst = sB + k * 256 + ((c >> 3) << 7)
                             + (((c & 7) ^ (k & 7)) << 4);
                cp16(dst, src, (n0 + c * 8 + 8 <= N) ? 16 : 0);
            }
        }
        CP_COMMIT();
    };

    // ldmatrix lane addressing
    const int aRow = wm + (lane & 15);
    const int aKsel = lane >> 4;
    const int swz = lane & 7;
    // non-trans B
    const int bRow = wn + ((lane >> 4) << 3) + (lane & 7);
    const int bKsel = (lane >> 3) & 1;
    // trans B: lane -> k row within k16, plus two n-octet byte offsets
    const int kLane = ((lane >> 3) & 1) * 8 + (lane & 7);
    int bOffT0 = 0, bOffT1 = 0;
    {
        int n0l = wn + ((lane >> 4) << 3);
        int c0 = n0l >> 3, c1 = (n0l + 16) >> 3;
        bOffT0 = ((c0 >> 3) << 7) + (((c0 & 7) ^ (lane & 7)) << 4);
        bOffT1 = ((c1 >> 3) << 7) + (((c1 & 7) ^ (lane & 7)) << 4);
    }

    // prologue: distance-2 prefetch
    load_stage(0, 0);
    load_stage(1, 1);

    for (int i = 0; i < nch; i++) {
        CP_WAIT(1);                  // stage i resident (<=1 group pending)
        __syncthreads();             // all warps done with stage (i-1) reads
        const int j = i + 2;
        if (j < nch) load_stage(j, j % NSTAGE);  // writes (i+2)%3 != i%3,(i+1)%3
        else         CP_COMMIT();    // keep group accounting aligned

        const uint32_t sA = sbase + (i % NSTAGE) * SSZ;
        const uint32_t sB = sA + ASZ;
        #pragma unroll
        for (int kk = 0; kk < 4; kk++) {
            uint32_t a[4][4], b[2][4];
            const uint32_t aByte = ((2 * kk + aKsel) ^ swz) << 4;
            #pragma unroll
            for (int mf = 0; mf < 4; mf++)
                LDSM_X4(a[mf], sA + (aRow + 16 * mf) * 128 + aByte);
            if constexpr (!TRANSB) {
                const uint32_t bByte = ((2 * kk + bKsel) ^ swz) << 4;
                #pragma unroll
                for (int nf2 = 0; nf2 < 2; nf2++)
                    LDSM_X4(b[nf2], sB + (bRow + 16 * nf2) * 128 + bByte);
            } else {
                const uint32_t rowB = sB + (kk * 16 + kLane) * 256;
                LDSM_X4_T(b[0], rowB + bOffT0);
                LDSM_X4_T(b[1], rowB + bOffT1);
            }
            #pragma unroll
            for (int mf = 0; mf < 4; mf++)
                #pragma unroll
                for (int nf = 0; nf < 4; nf++)
                    mma16816(acc[mf][nf], a[mf],
                             b[nf >> 1][(nf & 1) * 2],
                             b[nf >> 1][(nf & 1) * 2 + 1]);
        }
    }

    // ---- epilogue ----
    #pragma unroll
    for (int mf = 0; mf < 4; mf++) {
        const int row = m0 + wm + mf * 16 + (lane >> 2);
        #pragma unroll
        for (int nf = 0; nf < 4; nf++) {
            const int col = n0 + wn + nf * 8 + 2 * (lane & 3);
            if (col >= N) continue;
            float2 lo = make_float2(acc[mf][nf][0], acc[mf][nf][1]);
            float2 hi = make_float2(acc[mf][nf][2], acc[mf][nf][3]);
            if (HAS_BIAS) {
                float2 bb = *reinterpret_cast<const float2*>(bias + col);
                lo.x += bb.x; lo.y += bb.y;
                hi.x += bb.x; hi.y += bb.y;
            }
            if (ACT == ACT_RELU) {
                lo.x = fmaxf(lo.x, 0.f); lo.y = fmaxf(lo.y, 0.f);
                hi.x = fmaxf(hi.x, 0.f); hi.y = fmaxf(hi.y, 0.f);
            } else if (ACT == ACT_SIG) {
                lo.x = 1.f / (1.f + __expf(-lo.x));
                lo.y = 1.f / (1.f + __expf(-lo.y));
                hi.x = 1.f / (1.f + __expf(-hi.x));
                hi.y = 1.f / (1.f + __expf(-hi.y));
            } else if (ACT == ACT_NEG) {
                lo.x = -lo.x; lo.y = -lo.y;
                hi.x = -hi.x; hi.y = -hi.y;
            }  // ACT_NONE: raw
            if (OUT_HALF) {
                __half* C = (__half*)Cout;
                *reinterpret_cast<__half2*>(C + (size_t)row * N + col) =
                    __floats2half2_rn(lo.x, lo.y);
                *reinterpret_cast<__half2*>(C + (size_t)(row + 8) * N + col) =
                    __floats2half2_rn(hi.x, hi.y);
            } else {
                float* C = (float*)Cout;
                *reinterpret_cast<float2*>(C + (size_t)row * N + col) = lo;
                *reinterpret_cast<float2*>(C + (size_t)(row + 8) * N + col) = hi;
            }
        }
    }
}

// ---------------------------------------------------------------------------
// Standalone GEMM kernel (with dual-pointer wave-merge mode)
// ---------------------------------------------------------------------------
template<int ACT, bool HAS_BIAS, bool OUT_HALF, bool TRANSB>
__global__ __launch_bounds__(256, 2)
void hmma_gemm(const __half* __restrict__ Ap, const __half* __restrict__ Bp,
               const float* __restrict__ biasp, void* __restrict__ Coutp,
               int M, int N, int K, int lda, int ldb,
               const __half* A2, const __half* B2,
               const float* bias2, void* Cout2, int nSplit) {
    extern __shared__ __align__(128) char smem[];
    const __half* A   = Ap;
    const __half* Bt  = Bp;
    const float* bias = biasp;
    void* Cout        = Coutp;
    int by = blockIdx.y;
    if (by >= nSplit) {
        by -= nSplit;
        A = A2; Bt = B2; bias = bias2; Cout = Cout2;
    }
    gemm_body<ACT, HAS_BIAS, OUT_HALF, TRANSB>(
        A, Bt, bias, Cout, M, N, K, lda, ldb, blockIdx.x, by, smem);
}

// ---------------------------------------------------------------------------
// Aux device helpers (block-indexed bodies of the prep kernels)
// ---------------------------------------------------------------------------
__device__ __forceinline__ void aux_popular_reduce(
    int b, const float* __restrict__ part, float* __restrict__ out_pop) {
    int i = b * 256 + threadIdx.x;
    if (i >= NITEMS) return;
    float s = 0.f;
    #pragma unroll
    for (int c = 0; c < 16; c++) s += part[c * NITEMS + i];
    out_pop[i] = s * (1.0f / (float)BATCH);
}

__device__ __forceinline__ void aux_convert_pad(
    int b, const float* __restrict__ in, __half* __restrict__ out,
    long validElems, long total8) {
    long i = (long)b * 256 + threadIdx.x;
    if (i >= total8) return;
    long e = i * 8;
    __half2 h[4];
    if (e + 8 <= validElems) {
        float4 a = *reinterpret_cast<const float4*>(in + e);
        float4 bb = *reinterpret_cast<const float4*>(in + e + 4);
        h[0] = __floats2half2_rn(a.x, a.y);
        h[1] = __floats2half2_rn(a.z, a.w);
        h[2] = __floats2half2_rn(bb.x, bb.y);
        h[3] = __floats2half2_rn(bb.z, bb.w);
    } else {
        h[0] = h[1] = h[2] = h[3] = __floats2half2_rn(0.f, 0.f);
    }
    __half2* dst = reinterpret_cast<__half2*>(out + e);
    dst[0] = h[0]; dst[1] = h[1]; dst[2] = h[2]; dst[3] = h[3];
}

__device__ __forceinline__ void aux_convert_cols(
    int b, const float* __restrict__ in, __half* __restrict__ out,
    int C, int ldo, int colOff, int total8) {
    int i = b * 256 + threadIdx.x;
    if (i >= total8) return;
    long e = (long)i * 8;
    int k = (int)(e / C);
    int c = (int)(e - (long)k * C);
    float4 a = *reinterpret_cast<const float4*>(in + e);
    float4 bb = *reinterpret_cast<const float4*>(in + e + 4);
    __half2* dst = reinterpret_cast<__half2*>(out + (size_t)k * ldo + colOff + c);
    dst[0] = __floats2half2_rn(a.x, a.y);
    dst[1] = __floats2half2_rn(a.z, a.w);
    dst[2] = __floats2half2_rn(bb.x, bb.y);
    dst[3] = __floats2half2_rn(bb.z, bb.w);
}

__device__ __forceinline__ void aux_concat2(
    int b, const float* __restrict__ a, const float* __restrict__ bsrc,
    float* __restrict__ o, int n) {
    int i = b * 256 + threadIdx.x;
    if (i < n) o[i] = a[i];
    else if (i < 2 * n) o[i] = bsrc[i - n];
}

// ---------------------------------------------------------------------------
// MEGA kernel: split-K gemm1 (bids 0..255) + ALL independent prep work
// ---------------------------------------------------------------------------
#define MEGA_GEMM 256
#define AUX_RED   79
#define AUX_W2    256
#define AUX_WLR1  256
#define AUX_WLR2  256
#define AUX_BLR   8
#define AUX_W4    10000
#define AUX_W6    10000
#define MEGA_BLOCKS (MEGA_GEMM + AUX_RED + AUX_W2 + AUX_WLR1 + AUX_WLR2 + \
                     AUX_BLR + AUX_W4 + AUX_W6)

__global__ __launch_bounds__(256, 2)
void mega_kernel(const __half* __restrict__ noisyh,
                 const __half* __restrict__ W1c, float* __restrict__ psum,
                 const float* __restrict__ part, float* __restrict__ out_pop,
                 const float* __restrict__ enc_w2, __half* __restrict__ W2c,
                 const float* __restrict__ lk_w1, const float* __restrict__ rc_w1,
                 __half* __restrict__ Wlr,
                 const float* __restrict__ lk_b1, const float* __restrict__ rc_b1,
                 float* __restrict__ blr,
                 const float* __restrict__ lk_w2, __half* __restrict__ W4c,
                 const float* __restrict__ rc_w2, __half* __restrict__ W6c) {
    extern __shared__ __align__(128) char smem[];
    int bid = blockIdx.x;
    if (bid < MEGA_GEMM) {
        int z = bid >> 7;            // K split 0/1
        int bx = bid & 15;           // m tile
        int by = (bid >> 4) & 7;     // n tile
        const __half* A = noisyh + (size_t)z * KHALF;
        const __half* B = W1c + (size_t)z * KHALF * HID;
        float* C = psum + (size_t)z * BATCH * HID;
        gemm_body<ACT_NONE, false, false, true>(
            A, B, nullptr, C, BATCH, HID, KHALF, KPAD, HID, bx, by, smem);
        return;
    }
    int aux = bid - MEGA_GEMM;
    if (aux < AUX_RED) { aux_popular_reduce(aux, part, out_pop); return; }
    aux -= AUX_RED;
    if (aux < AUX_W2) {
        aux_convert_pad(aux, enc_w2, W2c, (long)HID * EMB, (long)HID * EMB / 8);
        return;
    }
    aux -= AUX_W2;
    if (aux < AUX_WLR1) {
        aux_convert_cols(aux, lk_w1, Wlr, HID, 2 * HID, 0, EMB * HID / 8);
        return;
    }
    aux -= AUX_WLR1;
    if (aux < AUX_WLR2) {
        aux_convert_cols(aux, rc_w1, Wlr, HID, 2 * HID, HID, EMB * HID / 8);
        return;
    }
    aux -= AUX_WLR2;
    if (aux < AUX_BLR) { aux_concat2(aux, lk_b1, rc_b1, blr, HID); return; }
    aux -= AUX_BLR;
    if (aux < AUX_W4) {
        aux_convert_pad(aux, lk_w2, W4c, (long)HID * NITEMS,
                        (long)HID * NITEMS / 8);
        return;
    }
    aux -= AUX_W4;
    aux_convert_pad(aux, rc_w2, W6c, (long)HID * NITEMS,
                    (long)HID * NITEMS / 8);
}

// ---------------------------------------------------------------------------
// Small kernels
// ---------------------------------------------------------------------------
__global__ void probe_mask_kernel(const unsigned int* __restrict__ w) {
    __shared__ int s_other, s_f1, s_i1;
    if (threadIdx.x == 0) { s_other = 0; s_f1 = 0; s_i1 = 0; }
    __syncthreads();
    int lo = 0, lf = 0, li = 0;
    for (int i = threadIdx.x; i < 65536; i += blockDim.x) {
        unsigned v = w[i];
        if (v == 0u) continue;
        else if (v == 1u) li++;
        else if (v == 0x3F800000u) lf++;
        else lo++;
    }
    atomicAdd(&s_other, lo); atomicAdd(&s_f1, lf); atomicAdd(&s_i1, li);
    __syncthreads();
    if (threadIdx.x == 0) {
        int mode;
        if (s_other > 1024) mode = 0;
        else if (s_f1 >= s_i1) mode = 2;
        else mode = 1;
        g_mask_mode = mode;
    }
}

// Fused: noisy = where(mask,0,likes) -> fp16 padded AND column partial sums
__global__ void premask_popular_kernel(const float* __restrict__ likes,
                                       const void* __restrict__ mask,
                                       __half* __restrict__ noisy,
                                       float* __restrict__ part) {
    const int mode = g_mask_mode;
    const int col = blockIdx.x * 256 + threadIdx.x;
    if (col >= KPAD) return;
    const int r0 = blockIdx.y * 128;

    if (col >= NITEMS) {  // padding region: zero noisy, no popular
        const __half hz = __float2half_rn(0.f);
        for (int r = 0; r < 128; r++)
            noisy[(size_t)(r0 + r) * KPAD + col] = hz;
        return;
    }

    const unsigned char* m8 = (const unsigned char*)mask;
    const int*           mi = (const int*)mask;
    const float*         mf = (const float*)mask;

    float sum = 0.f;
    #pragma unroll 4
    for (int r = 0; r < 128; r++) {
        size_t e = (size_t)(r0 + r) * NITEMS + col;
        float v = likes[e];
        sum += v;
        bool drop;
        if (mode == 0)      drop = (m8[e] != 0);
        else if (mode == 1) drop = (mi[e] != 0);
        else                drop = (mf[e] != 0.f);
        noisy[(size_t)(r0 + r) * KPAD + col] = __float2half_rn(drop ? 0.f : v);
    }
    part[blockIdx.y * NITEMS + col] = sum;
}

// combine split-K partials: Hh = fp16(relu(p0 + p1 + bias))
__global__ void combine_splitk_kernel(const float* __restrict__ p,
                                      const float* __restrict__ bias,
                                      __half* __restrict__ out) {
    const size_t MN = (size_t)BATCH * HID;
    size_t e = ((size_t)blockIdx.x * 256 + threadIdx.x) * 4;
    if (e >= MN) return;
    int col = (int)(e & (HID - 1));
    float4 a = *reinterpret_cast<const float4*>(p + e);
    float4 b = *reinterpret_cast<const float4*>(p + MN + e);
    float4 bb = *reinterpret_cast<const float4*>(bias + col);
    float x0 = fmaxf(a.x + b.x + bb.x, 0.f);
    float x1 = fmaxf(a.y + b.y + bb.y, 0.f);
    float x2 = fmaxf(a.z + b.z + bb.z, 0.f);
    float x3 = fmaxf(a.w + b.w + bb.w, 0.f);
    __half2* dst = reinterpret_cast<__half2*>(out + e);
    dst[0] = __floats2half2_rn(x0, x1);
    dst[1] = __floats2half2_rn(x2, x3);
}

// per-row l2 normalize; emit fp16 normalized AND fp16 copy of E
__global__ void norm_half_kernel(const float* __restrict__ E,
                                 __half* __restrict__ Nrmh,
                                 __half* __restrict__ Eh) {
    int row = blockIdx.x;
    int t = threadIdx.x;
    float4 v = reinterpret_cast<const float4*>(E + (size_t)row * EMB)[t];
    float ss = v.x * v.x + v.y * v.y + v.z * v.z + v.w * v.w;
    #pragma unroll
    for (int o = 16; o > 0; o >>= 1)
        ss += __shfl_xor_sync(0xFFFFFFFFu, ss, o);
    __shared__ float ws[4];
    if ((t & 31) == 0) ws[t >> 5] = ss;
    __syncthreads();
    float tot = ws[0] + ws[1] + ws[2] + ws[3];
    float inv = rsqrtf(fmaxf(tot, 1e-12f));
    __half2* eh = reinterpret_cast<__half2*>(Eh + (size_t)row * EMB + t * 4);
    eh[0] = __floats2half2_rn(v.x, v.y);
    eh[1] = __floats2half2_rn(v.z, v.w);
    __half2* nh = reinterpret_cast<__half2*>(Nrmh + (size_t)row * EMB + t * 4);
    nh[0] = __floats2half2_rn(v.x * inv, v.y * inv);
    nh[1] = __floats2half2_rn(v.z * inv, v.w * inv);
}

// f32 -> fp16 convert, contiguous, zero-padded beyond validElems (W1c only)
__global__ void convert_pad_kernel(const float* __restrict__ in,
                                   __half* __restrict__ out,
                                   long validElems, long total8) {
    long i = (long)blockIdx.x * blockDim.x + threadIdx.x;
    if (i >= total8) return;
    aux_convert_pad((int)blockIdx.x, in, out, validElems, total8);
}

#define NO_DUAL nullptr, nullptr, nullptr, nullptr, 0x40000000

// ---------------------------------------------------------------------------
// Launch (serial; MEGA is the 4th launch so ncu profiles it)
// ---------------------------------------------------------------------------
extern "C" void kernel_launch(void* const* d_in, const int* in_sizes, int n_in,
                              void* d_out, int out_size) {
    const float* likes  = (const float*)d_in[1];
    const void*  nmask  = d_in[2];
    const float* enc_w1 = (const float*)d_in[3];
    const float* enc_b1 = (const float*)d_in[4];
    const float* enc_w2 = (const float*)d_in[5];
    const float* enc_b2 = (const float*)d_in[6];
    const float* lk_w1  = (const float*)d_in[7];
    const float* lk_b1  = (const float*)d_in[8];
    const float* lk_w2  = (const float*)d_in[9];
    const float* lk_b2  = (const float*)d_in[10];
    const float* rc_w1  = (const float*)d_in[11];
    const float* rc_b1  = (const float*)d_in[12];
    const float* rc_w2  = (const float*)d_in[13];
    const float* rc_b2  = (const float*)d_in[14];

    float* out       = (float*)d_out;
    float* out_likes = out;
    float* out_sim   = out_likes + (size_t)BATCH * NITEMS;
    float* out_rec   = out_sim + (size_t)BATCH * BATCH;
    float* out_pop   = out_rec + (size_t)BATCH * NITEMS;

    __half *noisyh, *W1c, *W2c, *Wlr, *W4c, *W6c, *Hh, *Hh2, *Eh, *Nrmh;
    float *E, *part, *blr, *psum;
    cudaGetSymbolAddress((void**)&noisyh, g_noisyh);
    cudaGetSymbolAddress((void**)&W1c, g_W1c);
    cudaGetSymbolAddress((void**)&W2c, g_W2c);
    cudaGetSymbolAddress((void**)&Wlr, g_Wlr);
    cudaGetSymbolAddress((void**)&W4c, g_W4c);
    cudaGetSymbolAddress((void**)&W6c, g_W6c);
    cudaGetSymbolAddress((void**)&blr, g_blr);
    cudaGetSymbolAddress((void**)&psum, g_psum);
    cudaGetSymbolAddress((void**)&Hh, g_Hh);
    cudaGetSymbolAddress((void**)&Hh2, g_Hh2);
    cudaGetSymbolAddress((void**)&E, g_E);
    cudaGetSymbolAddress((void**)&Eh, g_Eh);
    cudaGetSymbolAddress((void**)&Nrmh, g_Nrmh);
    cudaGetSymbolAddress((void**)&part, g_part);

    const int smem = NSTAGE * SSZ;  // 96KB
    cudaFuncSetAttribute(mega_kernel,
                         cudaFuncAttributeMaxDynamicSharedMemorySize, smem);
    cudaFuncSetAttribute(hmma_gemm<ACT_RELU, true, false, true>,
                         cudaFuncAttributeMaxDynamicSharedMemorySize, smem);
    cudaFuncSetAttribute(hmma_gemm<ACT_RELU, true, true, true>,
                         cudaFuncAttributeMaxDynamicSharedMemorySize, smem);
    cudaFuncSetAttribute(hmma_gemm<ACT_SIG, true, false, true>,
                         cudaFuncAttributeMaxDynamicSharedMemorySize, smem);
    cudaFuncSetAttribute(hmma_gemm<ACT_NEG, false, false, false>,
                         cudaFuncAttributeMaxDynamicSharedMemorySize, smem);

    // 1: mask probe
    probe_mask_kernel<<<1, 256>>>((const unsigned int*)nmask);
    // 2: fused denoise + popular partials
    premask_popular_kernel<<<dim3((KPAD + 255) / 256, 16), 256>>>(
        likes, nmask, noisyh, part);
    // 3: convert enc_w1 -> fp16 [20096][1024] (zero-pad rows); gemm1 needs it
    {
        long valid = (long)NITEMS * HID;
        long tot8 = (long)KPAD * HID / 8;
        convert_pad_kernel<<<(int)((tot8 + 255) / 256), 256>>>(
            enc_w1, W1c, valid, tot8);
    }
    // 4: MEGA -- split-K gemm1 + all independent prep work (profiled)
    mega_kernel<<<MEGA_BLOCKS, 256, smem>>>(
        noisyh, W1c, psum, part, out_pop,
        enc_w2, W2c, lk_w1, rc_w1, Wlr, lk_b1, rc_b1, blr,
        lk_w2, W4c, rc_w2, W6c);
    // 5: combine partials -> Hh = fp16(relu(p0+p1+b1))
    combine_splitk_kernel<<<(int)(((size_t)BATCH * HID / 4 + 255) / 256), 256>>>(
        psum, enc_b1, Hh);

    // encoder layer 2 + norm
    hmma_gemm<ACT_RELU, true, false, true>
        <<<dim3(BATCH / 128, EMB / 128), 256, smem>>>(
        Hh, W2c, enc_b2, E, BATCH, EMB, HID, HID, EMB, NO_DUAL);
    norm_half_kernel<<<BATCH, 128>>>(E, Nrmh, Eh);

    // user_sim = -(Nrm @ Nrm^T)   (K-major B path)
    hmma_gemm<ACT_NEG, false, false, false>
        <<<dim3(BATCH / 128, BATCH / 128), 256, smem>>>(
        Nrmh, Nrmh, nullptr, out_sim, BATCH, BATCH, EMB, EMB, EMB, NO_DUAL);

    // fused head hiddens: Hh2 = relu(Eh @ [lk_w1 | rc_w1] + [b|b])  [2048][2048]
    hmma_gemm<ACT_RELU, true, true, true>
        <<<dim3(BATCH / 128, (2 * HID) / 128), 256, smem>>>(
        Eh, Wlr, blr, Hh2, BATCH, 2 * HID, EMB, EMB, 2 * HID, NO_DUAL);

    // BOTH head outputs in ONE launch (wave merge): y-tiles [0,157) likes,
    // [157,314) rec. 5024 CTAs = 16.97 waves.
    const int nTiles = (NITEMS + 127) / 128;  // 157
    hmma_gemm<ACT_SIG, true, false, true>
        <<<dim3(BATCH / 128, 2 * nTiles), 256, smem>>>(
        Hh2, W4c, lk_b2, out_likes, BATCH, NITEMS, HID, 2 * HID, NITEMS,
        Hh2 + HID, W6c, rc_b2, out_rec, nTiles);
}

// round 13
// speedup vs baseline: 1.2818x; 1.0390x over previous
#include <cuda_runtime.h>
#include <cuda_fp16.h>
#include <cstdint>

// Problem constants
#define BATCH  2048
#define NITEMS 20000
#define KPAD   20096   // NITEMS padded to 2 x 10048 (157 x 64 per K-split)
#define KHALF  10048
#define EMB    512
#define HID    1024    // 2*D

// ---------------------------------------------------------------------------
// Scratch (no allocations -> __device__ globals)
// ---------------------------------------------------------------------------
__device__ __half g_noisyh[(size_t)BATCH * KPAD];    // masked likes fp16, padded
__device__ __half g_W1c[(size_t)KPAD * HID];         // enc_w1 fp16 [20096][1024]
__device__ __half g_W2c[(size_t)HID * EMB];          // enc_w2 fp16 [1024][512]
__device__ __half g_Wlr[(size_t)EMB * (2 * HID)];    // [512][2048] = lk_w1 ++ rc_w1
__device__ __half g_W4c[(size_t)HID * NITEMS];       // lk_w2 fp16 [1024][20000]
__device__ __half g_W6c[(size_t)HID * NITEMS];       // rc_w2 fp16 [1024][20000]
__device__ float  g_blr[2 * HID];                    // lk_b1 ++ rc_b1
__device__ float  g_psum[2 * (size_t)BATCH * HID];   // split-K partials (f32)
__device__ __half g_Hh[(size_t)BATCH * HID];         // encoder hidden fp16
__device__ __half g_Hh2[(size_t)BATCH * 2 * HID];    // fused head hiddens fp16
__device__ float  g_E[(size_t)BATCH * EMB];          // embed f32
__device__ __half g_Eh[(size_t)BATCH * EMB];         // embed fp16
__device__ __half g_Nrmh[(size_t)BATCH * EMB];       // normalized fp16
__device__ float  g_part[16 * NITEMS];
__device__ int    g_mask_mode;  // 0=u8, 1=i32, 2=f32

// ---------------------------------------------------------------------------
// PTX helpers (arch-generic sm_80-era instructions)
// ---------------------------------------------------------------------------
__device__ __forceinline__ uint32_t smem_u32(const void* p) {
    uint32_t a;
    asm("{ .reg .u64 t; cvta.to.shared.u64 t, %1; cvt.u32.u64 %0, t; }"
        : "=r"(a) : "l"(p));
    return a;
}
__device__ __forceinline__ void cp16(uint32_t dst, const void* src, int sz) {
    asm volatile("cp.async.cg.shared.global [%0], [%1], 16, %2;"
        :: "r"(dst), "l"(src), "r"(sz));
}
#define CP_COMMIT() asm volatile("cp.async.commit_group;" ::: "memory")
#define CP_WAIT(n)  asm volatile("cp.async.wait_group %0;" :: "n"(n) : "memory")

#define LDSM_X4(r, addr) \
    asm volatile("ldmatrix.sync.aligned.m8n8.x4.shared.b16 {%0,%1,%2,%3}, [%4];" \
        : "=r"((r)[0]), "=r"((r)[1]), "=r"((r)[2]), "=r"((r)[3]) : "r"(addr))

#define LDSM_X4_T(r, addr) \
    asm volatile("ldmatrix.sync.aligned.m8n8.x4.trans.shared.b16 {%0,%1,%2,%3}, [%4];" \
        : "=r"((r)[0]), "=r"((r)[1]), "=r"((r)[2]), "=r"((r)[3]) : "r"(addr))

__device__ __forceinline__ void mma16816(float* d, const uint32_t* a,
                                         uint32_t b0, uint32_t b1) {
    asm volatile(
        "mma.sync.aligned.m16n8k16.row.col.f32.f16.f16.f32 "
        "{%0,%1,%2,%3}, {%4,%5,%6,%7}, {%8,%9}, {%0,%1,%2,%3};"
        : "+f"(d[0]), "+f"(d[1]), "+f"(d[2]), "+f"(d[3])
        : "r"(a[0]), "r"(a[1]), "r"(a[2]), "r"(a[3]), "r"(b0), "r"(b1));
}

enum { ACT_RELU = 0, ACT_SIG = 1, ACT_NEG = 2, ACT_NONE = 3 };
#define BK 64
#define NSTAGE 3
#define ASZ 16384                 // A: 128 rows * 128B ; B(trans): 64 rows * 256B
#define SSZ 32768                 // A + B per stage

// ---------------------------------------------------------------------------
// GEMM body. Single __syncthreads per K-chunk: 3 smem stages, prefetch
// distance 2 (stage written at iter i is (i+2)%3, last read at i-1).
// ---------------------------------------------------------------------------
template<int ACT, bool HAS_BIAS, bool OUT_HALF, bool TRANSB>
__device__ __forceinline__ void gemm_body(
    const __half* __restrict__ A, const __half* __restrict__ Bt,
    const float* __restrict__ bias, void* __restrict__ Cout,
    int M, int N, int K, int lda, int ldb, int bx, int by, char* smem) {
    const uint32_t sbase = smem_u32(smem);

    const int tid = threadIdx.x;
    const int lane = tid & 31, wid = tid >> 5;
    const int wm = (wid & 1) * 64;        // warp m offset in tile
    const int wn = (wid >> 1) * 32;       // warp n offset in tile
    const int m0 = bx * 128;
    const int n0 = by * 128;
    const int nch = K / BK;

    float acc[4][4][4];
    #pragma unroll
    for (int i = 0; i < 4; i++)
        #pragma unroll
        for (int j = 0; j < 4; j++)
            #pragma unroll
            for (int q = 0; q < 4; q++) acc[i][j][q] = 0.f;

    // ---- stage loader ----
    auto load_stage = [&](int ch, int st) {
        const int k0 = ch * BK;
        const uint32_t sA = sbase + st * SSZ;
        const uint32_t sB = sA + ASZ;
        #pragma unroll
        for (int u = 0; u < 4; u++) {
            int idx = tid + u * 256;
            int r = idx >> 3, c = idx & 7;
            const __half* src = A + (size_t)(m0 + r) * lda + k0 + c * 8;
            cp16(sA + r * 128 + ((c ^ (r & 7)) << 4), src, 16);
        }
        if constexpr (!TRANSB) {
            #pragma unroll
            for (int u = 0; u < 4; u++) {
                int idx = tid + u * 256;
                int r = idx >> 3, c = idx & 7;
                int n = n0 + r;
                const __half* src = Bt + (size_t)n * ldb + k0 + c * 8;
                cp16(sB + r * 128 + ((c ^ (r & 7)) << 4), src, (n < N) ? 16 : 0);
            }
        } else {
            // B tile [BK=64 k-rows][128 n], 256B per k-row, per-128B-half swizzle
            #pragma unroll
            for (int u = 0; u < 4; u++) {
                int idx = tid + u * 256;
                int k = idx >> 4, c = idx & 15;
                const __half* src = Bt + (size_t)(k0 + k) * ldb + n0 + c * 8;
                uint32_t dst = sB + k * 256 + ((c >> 3) << 7)
                             + (((c & 7) ^ (k & 7)) << 4);
                cp16(dst, src, (n0 + c * 8 + 8 <= N) ? 16 : 0);
            }
        }
        CP_COMMIT();
    };

    // ldmatrix lane addressing
    const int aRow = wm + (lane & 15);
    const int aKsel = lane >> 4;
    const int swz = lane & 7;
    // non-trans B
    const int bRow = wn + ((lane >> 4) << 3) + (lane & 7);
    const int bKsel = (lane >> 3) & 1;
    // trans B: lane -> k row within k16, plus two n-octet byte offsets
    const int kLane = ((lane >> 3) & 1) * 8 + (lane & 7);
    int bOffT0 = 0, bOffT1 = 0;
    {
        int n0l = wn + ((lane >> 4) << 3);
        int c0 = n0l >> 3, c1 = (n0l + 16) >> 3;
        bOffT0 = ((c0 >> 3) << 7) + (((c0 & 7) ^ (lane & 7)) << 4);
        bOffT1 = ((c1 >> 3) << 7) + (((c1 & 7) ^ (lane & 7)) << 4);
    }

    // prologue: distance-2 prefetch
    load_stage(0, 0);
    load_stage(1, 1);

    for (int i = 0; i < nch; i++) {
        CP_WAIT(1);                  // stage i resident (<=1 group pending)
        __syncthreads();             // all warps done with stage (i-1) reads
        const int j = i + 2;
        if (j < nch) load_stage(j, j % NSTAGE);
        else         CP_COMMIT();    // keep group accounting aligned

        const uint32_t sA = sbase + (i % NSTAGE) * SSZ;
        const uint32_t sB = sA + ASZ;
        #pragma unroll
        for (int kk = 0; kk < 4; kk++) {
            uint32_t a[4][4], b[2][4];
            const uint32_t aByte = ((2 * kk + aKsel) ^ swz) << 4;
            #pragma unroll
            for (int mf = 0; mf < 4; mf++)
                LDSM_X4(a[mf], sA + (aRow + 16 * mf) * 128 + aByte);
            if constexpr (!TRANSB) {
                const uint32_t bByte = ((2 * kk + bKsel) ^ swz) << 4;
                #pragma unroll
                for (int nf2 = 0; nf2 < 2; nf2++)
                    LDSM_X4(b[nf2], sB + (bRow + 16 * nf2) * 128 + bByte);
            } else {
                const uint32_t rowB = sB + (kk * 16 + kLane) * 256;
                LDSM_X4_T(b[0], rowB + bOffT0);
                LDSM_X4_T(b[1], rowB + bOffT1);
            }
            #pragma unroll
            for (int mf = 0; mf < 4; mf++)
                #pragma unroll
                for (int nf = 0; nf < 4; nf++)
                    mma16816(acc[mf][nf], a[mf],
                             b[nf >> 1][(nf & 1) * 2],
                             b[nf >> 1][(nf & 1) * 2 + 1]);
        }
    }

    // ---- epilogue ----
    #pragma unroll
    for (int mf = 0; mf < 4; mf++) {
        const int row = m0 + wm + mf * 16 + (lane >> 2);
        #pragma unroll
        for (int nf = 0; nf < 4; nf++) {
            const int col = n0 + wn + nf * 8 + 2 * (lane & 3);
            if (col >= N) continue;
            float2 lo = make_float2(acc[mf][nf][0], acc[mf][nf][1]);
            float2 hi = make_float2(acc[mf][nf][2], acc[mf][nf][3]);
            if (HAS_BIAS) {
                float2 bb = *reinterpret_cast<const float2*>(bias + col);
                lo.x += bb.x; lo.y += bb.y;
                hi.x += bb.x; hi.y += bb.y;
            }
            if (ACT == ACT_RELU) {
                lo.x = fmaxf(lo.x, 0.f); lo.y = fmaxf(lo.y, 0.f);
                hi.x = fmaxf(hi.x, 0.f); hi.y = fmaxf(hi.y, 0.f);
            } else if (ACT == ACT_SIG) {
                // fast sigmoid: ex2.approx + rcp.approx (no precise-div NR seq)
                lo.x = __fdividef(1.f, 1.f + __expf(-lo.x));
                lo.y = __fdividef(1.f, 1.f + __expf(-lo.y));
                hi.x = __fdividef(1.f, 1.f + __expf(-hi.x));
                hi.y = __fdividef(1.f, 1.f + __expf(-hi.y));
            } else if (ACT == ACT_NEG) {
                lo.x = -lo.x; lo.y = -lo.y;
                hi.x = -hi.x; hi.y = -hi.y;
            }  // ACT_NONE: raw
            if (OUT_HALF) {
                __half* C = (__half*)Cout;
                *reinterpret_cast<__half2*>(C + (size_t)row * N + col) =
                    __floats2half2_rn(lo.x, lo.y);
                *reinterpret_cast<__half2*>(C + (size_t)(row + 8) * N + col) =
                    __floats2half2_rn(hi.x, hi.y);
            } else {
                float* C = (float*)Cout;
                *reinterpret_cast<float2*>(C + (size_t)row * N + col) = lo;
                *reinterpret_cast<float2*>(C + (size_t)(row + 8) * N + col) = hi;
            }
        }
    }
}

// ---------------------------------------------------------------------------
// Standalone GEMM kernel (with dual-pointer wave-merge mode)
// ---------------------------------------------------------------------------
template<int ACT, bool HAS_BIAS, bool OUT_HALF, bool TRANSB>
__global__ __launch_bounds__(256, 2)
void hmma_gemm(const __half* __restrict__ Ap, const __half* __restrict__ Bp,
               const float* __restrict__ biasp, void* __restrict__ Coutp,
               int M, int N, int K, int lda, int ldb,
               const __half* A2, const __half* B2,
               const float* bias2, void* Cout2, int nSplit) {
    extern __shared__ __align__(128) char smem[];
    const __half* A   = Ap;
    const __half* Bt  = Bp;
    const float* bias = biasp;
    void* Cout        = Coutp;
    int by = blockIdx.y;
    if (by >= nSplit) {
        by -= nSplit;
        A = A2; Bt = B2; bias = bias2; Cout = Cout2;
    }
    gemm_body<ACT, HAS_BIAS, OUT_HALF, TRANSB>(
        A, Bt, bias, Cout, M, N, K, lda, ldb, blockIdx.x, by, smem);
}

// ---------------------------------------------------------------------------
// Merged sim + head-hidden kernel (both depend only on norm; one launch
// kills a wave-quantization boundary: 2 x 0.86 waves -> 1.73 waves)
// ---------------------------------------------------------------------------
__global__ __launch_bounds__(256, 2)
void simhid_kernel(const __half* __restrict__ Nrmh, float* __restrict__ out_sim,
                   const __half* __restrict__ Eh, const __half* __restrict__ Wlr,
                   const float* __restrict__ blr, __half* __restrict__ Hh2) {
    extern __shared__ __align__(128) char smem[];
    int bid = blockIdx.x;
    if (bid < 256) {
        gemm_body<ACT_NEG, false, false, false>(
            Nrmh, Nrmh, nullptr, out_sim, BATCH, BATCH, EMB, EMB, EMB,
            bid & 15, bid >> 4, smem);
    } else {
        bid -= 256;
        gemm_body<ACT_RELU, true, true, true>(
            Eh, Wlr, blr, Hh2, BATCH, 2 * HID, EMB, EMB, 2 * HID,
            bid & 15, bid >> 4, smem);
    }
}

// ---------------------------------------------------------------------------
// Aux device helpers (block-indexed bodies of the prep kernels)
// ---------------------------------------------------------------------------
__device__ __forceinline__ void aux_popular_reduce(
    int b, const float* __restrict__ part, float* __restrict__ out_pop) {
    int i = b * 256 + threadIdx.x;
    if (i >= NITEMS) return;
    float s = 0.f;
    #pragma unroll
    for (int c = 0; c < 16; c++) s += part[c * NITEMS + i];
    out_pop[i] = s * (1.0f / (float)BATCH);
}

__device__ __forceinline__ void aux_convert_pad(
    int b, const float* __restrict__ in, __half* __restrict__ out,
    long validElems, long total8) {
    long i = (long)b * 256 + threadIdx.x;
    if (i >= total8) return;
    long e = i * 8;
    __half2 h[4];
    if (e + 8 <= validElems) {
        float4 a = *reinterpret_cast<const float4*>(in + e);
        float4 bb = *reinterpret_cast<const float4*>(in + e + 4);
        h[0] = __floats2half2_rn(a.x, a.y);
        h[1] = __floats2half2_rn(a.z, a.w);
        h[2] = __floats2half2_rn(bb.x, bb.y);
        h[3] = __floats2half2_rn(bb.z, bb.w);
    } else {
        h[0] = h[1] = h[2] = h[3] = __floats2half2_rn(0.f, 0.f);
    }
    __half2* dst = reinterpret_cast<__half2*>(out + e);
    dst[0] = h[0]; dst[1] = h[1]; dst[2] = h[2]; dst[3] = h[3];
}

__device__ __forceinline__ void aux_convert_cols(
    int b, const float* __restrict__ in, __half* __restrict__ out,
    int C, int ldo, int colOff, int total8) {
    int i = b * 256 + threadIdx.x;
    if (i >= total8) return;
    long e = (long)i * 8;
    int k = (int)(e / C);
    int c = (int)(e - (long)k * C);
    float4 a = *reinterpret_cast<const float4*>(in + e);
    float4 bb = *reinterpret_cast<const float4*>(in + e + 4);
    __half2* dst = reinterpret_cast<__half2*>(out + (size_t)k * ldo + colOff + c);
    dst[0] = __floats2half2_rn(a.x, a.y);
    dst[1] = __floats2half2_rn(a.z, a.w);
    dst[2] = __floats2half2_rn(bb.x, bb.y);
    dst[3] = __floats2half2_rn(bb.z, bb.w);
}

__device__ __forceinline__ void aux_concat2(
    int b, const float* __restrict__ a, const float* __restrict__ bsrc,
    float* __restrict__ o, int n) {
    int i = b * 256 + threadIdx.x;
    if (i < n) o[i] = a[i];
    else if (i < 2 * n) o[i] = bsrc[i - n];
}

// ---------------------------------------------------------------------------
// MEGA kernel: split-K gemm1 (bids 0..255) + ALL independent prep work
// ---------------------------------------------------------------------------
#define MEGA_GEMM 256
#define AUX_RED   79
#define AUX_W2    256
#define AUX_WLR1  256
#define AUX_WLR2  256
#define AUX_BLR   8
#define AUX_W4    10000
#define AUX_W6    10000
#define MEGA_BLOCKS (MEGA_GEMM + AUX_RED + AUX_W2 + AUX_WLR1 + AUX_WLR2 + \
                     AUX_BLR + AUX_W4 + AUX_W6)

__global__ __launch_bounds__(256, 2)
void mega_kernel(const __half* __restrict__ noisyh,
                 const __half* __restrict__ W1c, float* __restrict__ psum,
                 const float* __restrict__ part, float* __restrict__ out_pop,
                 const float* __restrict__ enc_w2, __half* __restrict__ W2c,
                 const float* __restrict__ lk_w1, const float* __restrict__ rc_w1,
                 __half* __restrict__ Wlr,
                 const float* __restrict__ lk_b1, const float* __restrict__ rc_b1,
                 float* __restrict__ blr,
                 const float* __restrict__ lk_w2, __half* __restrict__ W4c,
                 const float* __restrict__ rc_w2, __half* __restrict__ W6c) {
    extern __shared__ __align__(128) char smem[];
    int bid = blockIdx.x;
    if (bid < MEGA_GEMM) {
        int z = bid >> 7;            // K split 0/1
        int bx = bid & 15;           // m tile
        int by = (bid >> 4) & 7;     // n tile
        const __half* A = noisyh + (size_t)z * KHALF;
        const __half* B = W1c + (size_t)z * KHALF * HID;
        float* C = psum + (size_t)z * BATCH * HID;
        gemm_body<ACT_NONE, false, false, true>(
            A, B, nullptr, C, BATCH, HID, KHALF, KPAD, HID, bx, by, smem);
        return;
    }
    int aux = bid - MEGA_GEMM;
    if (aux < AUX_RED) { aux_popular_reduce(aux, part, out_pop); return; }
    aux -= AUX_RED;
    if (aux < AUX_W2) {
        aux_convert_pad(aux, enc_w2, W2c, (long)HID * EMB, (long)HID * EMB / 8);
        return;
    }
    aux -= AUX_W2;
    if (aux < AUX_WLR1) {
        aux_convert_cols(aux, lk_w1, Wlr, HID, 2 * HID, 0, EMB * HID / 8);
        return;
    }
    aux -= AUX_WLR1;
    if (aux < AUX_WLR2) {
        aux_convert_cols(aux, rc_w1, Wlr, HID, 2 * HID, HID, EMB * HID / 8);
        return;
    }
    aux -= AUX_WLR2;
    if (aux < AUX_BLR) { aux_concat2(aux, lk_b1, rc_b1, blr, HID); return; }
    aux -= AUX_BLR;
    if (aux < AUX_W4) {
        aux_convert_pad(aux, lk_w2, W4c, (long)HID * NITEMS,
                        (long)HID * NITEMS / 8);
        return;
    }
    aux -= AUX_W4;
    aux_convert_pad(aux, rc_w2, W6c, (long)HID * NITEMS,
                    (long)HID * NITEMS / 8);
}

// ---------------------------------------------------------------------------
// Small kernels
// ---------------------------------------------------------------------------
__global__ void probe_mask_kernel(const unsigned int* __restrict__ w) {
    __shared__ int s_other, s_f1, s_i1;
    if (threadIdx.x == 0) { s_other = 0; s_f1 = 0; s_i1 = 0; }
    __syncthreads();
    int lo = 0, lf = 0, li = 0;
    for (int i = threadIdx.x; i < 65536; i += blockDim.x) {
        unsigned v = w[i];
        if (v == 0u) continue;
        else if (v == 1u) li++;
        else if (v == 0x3F800000u) lf++;
        else lo++;
    }
    atomicAdd(&s_other, lo); atomicAdd(&s_f1, lf); atomicAdd(&s_i1, li);
    __syncthreads();
    if (threadIdx.x == 0) {
        int mode;
        if (s_other > 1024) mode = 0;
        else if (s_f1 >= s_i1) mode = 2;
        else mode = 1;
        g_mask_mode = mode;
    }
}

// Merged prep: premask+popular partials (bids 0..1263) + W1 convert (rest).
// Both DRAM-bound and independent; packing them removes a serial boundary.
#define PREM_X 79                       // ceil(KPAD/256)
#define PREM_BLOCKS (PREM_X * 16)       // 1264
#define W1_BLOCKS ((KPAD * HID / 8) / 256)  // 10048
#define PREP_BLOCKS (PREM_BLOCKS + W1_BLOCKS)

__global__ void prep_kernel(const float* __restrict__ likes,
                            const void* __restrict__ mask,
                            __half* __restrict__ noisy,
                            float* __restrict__ part,
                            const float* __restrict__ enc_w1,
                            __half* __restrict__ W1c) {
    int bid = blockIdx.x;
    if (bid >= PREM_BLOCKS) {
        aux_convert_pad(bid - PREM_BLOCKS, enc_w1, W1c,
                        (long)NITEMS * HID, (long)KPAD * HID / 8);
        return;
    }
    const int mode = g_mask_mode;
    const int col = (bid % PREM_X) * 256 + threadIdx.x;
    if (col >= KPAD) return;
    const int r0 = (bid / PREM_X) * 128;

    if (col >= NITEMS) {  // padding region: zero noisy, no popular
        const __half hz = __float2half_rn(0.f);
        for (int r = 0; r < 128; r++)
            noisy[(size_t)(r0 + r) * KPAD + col] = hz;
        return;
    }

    const unsigned char* m8 = (const unsigned char*)mask;
    const int*           mi = (const int*)mask;
    const float*         mf = (const float*)mask;

    float sum = 0.f;
    #pragma unroll 4
    for (int r = 0; r < 128; r++) {
        size_t e = (size_t)(r0 + r) * NITEMS + col;
        float v = likes[e];
        sum += v;
        bool drop;
        if (mode == 0)      drop = (m8[e] != 0);
        else if (mode == 1) drop = (mi[e] != 0);
        else                drop = (mf[e] != 0.f);
        noisy[(size_t)(r0 + r) * KPAD + col] = __float2half_rn(drop ? 0.f : v);
    }
    part[(bid / PREM_X) * NITEMS + col] = sum;
}

// combine split-K partials: Hh = fp16(relu(p0 + p1 + bias))
__global__ void combine_splitk_kernel(const float* __restrict__ p,
                                      const float* __restrict__ bias,
                                      __half* __restrict__ out) {
    const size_t MN = (size_t)BATCH * HID;
    size_t e = ((size_t)blockIdx.x * 256 + threadIdx.x) * 4;
    if (e >= MN) return;
    int col = (int)(e & (HID - 1));
    float4 a = *reinterpret_cast<const float4*>(p + e);
    float4 b = *reinterpret_cast<const float4*>(p + MN + e);
    float4 bb = *reinterpret_cast<const float4*>(bias + col);
    float x0 = fmaxf(a.x + b.x + bb.x, 0.f);
    float x1 = fmaxf(a.y + b.y + bb.y, 0.f);
    float x2 = fmaxf(a.z + b.z + bb.z, 0.f);
    float x3 = fmaxf(a.w + b.w + bb.w, 0.f);
    __half2* dst = reinterpret_cast<__half2*>(out + e);
    dst[0] = __floats2half2_rn(x0, x1);
    dst[1] = __floats2half2_rn(x2, x3);
}

// per-row l2 normalize; emit fp16 normalized AND fp16 copy of E
__global__ void norm_half_kernel(const float* __restrict__ E,
                                 __half* __restrict__ Nrmh,
                                 __half* __restrict__ Eh) {
    int row = blockIdx.x;
    int t = threadIdx.x;
    float4 v = reinterpret_cast<const float4*>(E + (size_t)row * EMB)[t];
    float ss = v.x * v.x + v.y * v.y + v.z * v.z + v.w * v.w;
    #pragma unroll
    for (int o = 16; o > 0; o >>= 1)
        ss += __shfl_xor_sync(0xFFFFFFFFu, ss, o);
    __shared__ float ws[4];
    if ((t & 31) == 0) ws[t >> 5] = ss;
    __syncthreads();
    float tot = ws[0] + ws[1] + ws[2] + ws[3];
    float inv = rsqrtf(fmaxf(tot, 1e-12f));
    __half2* eh = reinterpret_cast<__half2*>(Eh + (size_t)row * EMB + t * 4);
    eh[0] = __floats2half2_rn(v.x, v.y);
    eh[1] = __floats2half2_rn(v.z, v.w);
    __half2* nh = reinterpret_cast<__half2*>(Nrmh + (size_t)row * EMB + t * 4);
    nh[0] = __floats2half2_rn(v.x * inv, v.y * inv);
    nh[1] = __floats2half2_rn(v.z * inv, v.w * inv);
}

#define NO_DUAL nullptr, nullptr, nullptr, nullptr, 0x40000000

// ---------------------------------------------------------------------------
// Launch
// ---------------------------------------------------------------------------
extern "C" void kernel_launch(void* const* d_in, const int* in_sizes, int n_in,
                              void* d_out, int out_size) {
    const float* likes  = (const float*)d_in[1];
    const void*  nmask  = d_in[2];
    const float* enc_w1 = (const float*)d_in[3];
    const float* enc_b1 = (const float*)d_in[4];
    const float* enc_w2 = (const float*)d_in[5];
    const float* enc_b2 = (const float*)d_in[6];
    const float* lk_w1  = (const float*)d_in[7];
    const float* lk_b1  = (const float*)d_in[8];
    const float* lk_w2  = (const float*)d_in[9];
    const float* lk_b2  = (const float*)d_in[10];
    const float* rc_w1  = (const float*)d_in[11];
    const float* rc_b1  = (const float*)d_in[12];
    const float* rc_w2  = (const float*)d_in[13];
    const float* rc_b2  = (const float*)d_in[14];

    float* out       = (float*)d_out;
    float* out_likes = out;
    float* out_sim   = out_likes + (size_t)BATCH * NITEMS;
    float* out_rec   = out_sim + (size_t)BATCH * BATCH;
    float* out_pop   = out_rec + (size_t)BATCH * NITEMS;

    __half *noisyh, *W1c, *W2c, *Wlr, *W4c, *W6c, *Hh, *Hh2, *Eh, *Nrmh;
    float *E, *part, *blr, *psum;
    cudaGetSymbolAddress((void**)&noisyh, g_noisyh);
    cudaGetSymbolAddress((void**)&W1c, g_W1c);
    cudaGetSymbolAddress((void**)&W2c, g_W2c);
    cudaGetSymbolAddress((void**)&Wlr, g_Wlr);
    cudaGetSymbolAddress((void**)&W4c, g_W4c);
    cudaGetSymbolAddress((void**)&W6c, g_W6c);
    cudaGetSymbolAddress((void**)&blr, g_blr);
    cudaGetSymbolAddress((void**)&psum, g_psum);
    cudaGetSymbolAddress((void**)&Hh, g_Hh);
    cudaGetSymbolAddress((void**)&Hh2, g_Hh2);
    cudaGetSymbolAddress((void**)&E, g_E);
    cudaGetSymbolAddress((void**)&Eh, g_Eh);
    cudaGetSymbolAddress((void**)&Nrmh, g_Nrmh);
    cudaGetSymbolAddress((void**)&part, g_part);

    const int smem = NSTAGE * SSZ;  // 96KB
    cudaFuncSetAttribute(mega_kernel,
                         cudaFuncAttributeMaxDynamicSharedMemorySize, smem);
    cudaFuncSetAttribute(simhid_kernel,
                         cudaFuncAttributeMaxDynamicSharedMemorySize, smem);
    cudaFuncSetAttribute(hmma_gemm<ACT_RELU, true, false, true>,
                         cudaFuncAttributeMaxDynamicSharedMemorySize, smem);
    cudaFuncSetAttribute(hmma_gemm<ACT_SIG, true, false, true>,
                         cudaFuncAttributeMaxDynamicSharedMemorySize, smem);

    // 1: mask probe
    probe_mask_kernel<<<1, 256>>>((const unsigned int*)nmask);
    // 2: merged prep -- denoise+popular partials + enc_w1 convert
    prep_kernel<<<PREP_BLOCKS, 256>>>(likes, nmask, noisyh, part, enc_w1, W1c);
    // 3: MEGA -- split-K gemm1 + all remaining independent prep work
    mega_kernel<<<MEGA_BLOCKS, 256, smem>>>(
        noisyh, W1c, psum, part, out_pop,
        enc_w2, W2c, lk_w1, rc_w1, Wlr, lk_b1, rc_b1, blr,
        lk_w2, W4c, rc_w2, W6c);
    // 4: combine partials -> Hh = fp16(relu(p0+p1+b1))
    combine_splitk_kernel<<<(int)(((size_t)BATCH * HID / 4 + 255) / 256), 256>>>(
        psum, enc_b1, Hh);

    // 5: encoder layer 2
    hmma_gemm<ACT_RELU, true, false, true>
        <<<dim3(BATCH / 128, EMB / 128), 256, smem>>>(
        Hh, W2c, enc_b2, E, BATCH, EMB, HID, HID, EMB, NO_DUAL);
    // 6: norm
    norm_half_kernel<<<BATCH, 128>>>(E, Nrmh, Eh);

    // 7: merged sim + head-hidden (one launch, 512 CTAs)
    simhid_kernel<<<512, 256, smem>>>(Nrmh, out_sim, Eh, Wlr, blr, Hh2);

    // 8: BOTH head outputs in ONE launch (wave merge)
    const int nTiles = (NITEMS + 127) / 128;  // 157
    hmma_gemm<ACT_SIG, true, false, true>
        <<<dim3(BATCH / 128, 2 * nTiles), 256, smem>>>(
        Hh2, W4c, lk_b2, out_likes, BATCH, NITEMS, HID, 2 * HID, NITEMS,
        Hh2 + HID, W6c, rc_b2, out_rec, nTiles);
}